// round 9
// baseline (speedup 1.0000x reference)
#include <cuda_runtime.h>
#include <cuda_bf16.h>
#include <math.h>
#include <cstdint>

#define B_SZ   4
#define SEQ    1024
#define DM     1024
#define NH     16
#define DFF    2048
#define ROWS   (B_SZ*SEQ)        // 4096
#define LN_EPS 1e-5f

// GEMM smem: CTA tile 256x128, chunk k64. Row stride 144B (128B data + 16B pad).
// Per buffer: Ahi/Alo 256x144, Bhi/Blo 128x144. 2-stage.
#define ROWB      144
#define OFF_AHI   0
#define OFF_ALO   36864
#define OFF_BHI   73728
#define OFF_BLO   92160
#define BUF_B     110592
#define GSMEM     (2*BUF_B)      // 221184

// Attention smem: KV tile = 64 keys x 64 dims bf16 hi/lo, 144B row stride
#define AROWB     144
#define ATILE     (64*AROWB)
#define AKHI      0
#define AKLO      (ATILE)
#define AVHI      (2*ATILE)
#define AVLO      (3*ATILE)
#define ABUF      (4*ATILE)      // 36864
#define ASMEM     (2*ABUF)       // 73728

// ---------------- scratch (device globals) ----------------
__device__ float g_q[ROWS*DM];                     // Q fp32 (scaled at read)
__device__ float g_tmp[ROWS*DM];
__device__ float g_h[ROWS*DM];
__device__ float g_bqkv[3*DM];
__device__ __nv_bfloat16 g_khi[ROWS*DM],   g_klo[ROWS*DM];
__device__ __nv_bfloat16 g_vhi[ROWS*DM],   g_vlo[ROWS*DM];
__device__ __nv_bfloat16 g_xhi[ROWS*DM],   g_xlo[ROWS*DM];
__device__ __nv_bfloat16 g_ahi[ROWS*DM],   g_alo[ROWS*DM];        // attention out
__device__ __nv_bfloat16 g_hhi[ROWS*DM],   g_hlo[ROWS*DM];        // LN1 out
__device__ __nv_bfloat16 g_fhi[ROWS*DFF],  g_flo[ROWS*DFF];       // FF1 out
__device__ __nv_bfloat16 g_wqkvhi[3*DM*DM], g_wqkvlo[3*DM*DM];    // [3072 N][1024 K]
__device__ __nv_bfloat16 g_wohi[DM*DM],     g_wolo[DM*DM];
__device__ __nv_bfloat16 g_w1hi[DFF*DM],    g_w1lo[DFF*DM];
__device__ __nv_bfloat16 g_w2hi[DM*DFF],    g_w2lo[DM*DFF];

// =================================================================================
// helpers
// =================================================================================
__device__ __forceinline__ uint32_t smem_u32(const void* p) {
    uint32_t a;
    asm("{ .reg .u64 t; cvta.to.shared.u64 t, %1; cvt.u32.u64 %0, t; }" : "=r"(a) : "l"(p));
    return a;
}
__device__ __forceinline__ void ldsm4(uint32_t* r, uint32_t addr) {
    asm volatile("ldmatrix.sync.aligned.m8n8.x4.shared.b16 {%0,%1,%2,%3}, [%4];"
                 : "=r"(r[0]), "=r"(r[1]), "=r"(r[2]), "=r"(r[3]) : "r"(addr));
}
__device__ __forceinline__ void ldsm4t(uint32_t* r, uint32_t addr) {
    asm volatile("ldmatrix.sync.aligned.m8n8.x4.trans.shared.b16 {%0,%1,%2,%3}, [%4];"
                 : "=r"(r[0]), "=r"(r[1]), "=r"(r[2]), "=r"(r[3]) : "r"(addr));
}
__device__ __forceinline__ void mma_bf16(float* d, const uint32_t* a, uint32_t b0, uint32_t b1) {
    asm volatile("mma.sync.aligned.m16n8k16.row.col.f32.bf16.bf16.f32 "
                 "{%0,%1,%2,%3}, {%4,%5,%6,%7}, {%8,%9}, {%0,%1,%2,%3};"
                 : "+f"(d[0]), "+f"(d[1]), "+f"(d[2]), "+f"(d[3])
                 : "r"(a[0]), "r"(a[1]), "r"(a[2]), "r"(a[3]), "r"(b0), "r"(b1));
}
#define CP16(dst, src) asm volatile("cp.async.cg.shared.global [%0], [%1], 16;" :: "r"(dst), "l"(src))
#define CP_COMMIT()    asm volatile("cp.async.commit_group;" ::: "memory")
#define CP_WAIT(n)     asm volatile("cp.async.wait_group %0;" :: "n"(n) : "memory")

__device__ __forceinline__ void split2(float a, float b, uint32_t& hi, uint32_t& lo) {
    __nv_bfloat16 ah = __float2bfloat16(a);
    __nv_bfloat16 bh = __float2bfloat16(b);
    __nv_bfloat16 al = __float2bfloat16(a - __bfloat162float(ah));
    __nv_bfloat16 bl = __float2bfloat16(b - __bfloat162float(bh));
    __nv_bfloat162 h2; h2.x = ah; h2.y = bh;
    __nv_bfloat162 l2; l2.x = al; l2.y = bl;
    hi = *reinterpret_cast<uint32_t*>(&h2);
    lo = *reinterpret_cast<uint32_t*>(&l2);
}
__device__ __forceinline__ uint32_t packbf(float a, float b) {
    __nv_bfloat162 t; t.x = __float2bfloat16(a); t.y = __float2bfloat16(b);
    return *reinterpret_cast<uint32_t*>(&t);
}

// =================================================================================
// weight packing
// =================================================================================
__global__ void tsplit_k(const float* __restrict__ src,
                         __nv_bfloat16* __restrict__ dhi, __nv_bfloat16* __restrict__ dlo,
                         int R, int C)
{
    __shared__ float t[32][33];
    const int c0 = blockIdx.x * 32, r0 = blockIdx.y * 32;
    const int tx = threadIdx.x, ty = threadIdx.y;
    #pragma unroll
    for (int i = ty; i < 32; i += 8)
        t[i][tx] = src[(size_t)(r0 + i) * C + c0 + tx];
    __syncthreads();
    #pragma unroll
    for (int i = ty; i < 32; i += 8) {
        const float v = t[tx][i];
        const __nv_bfloat16 h = __float2bfloat16(v);
        const __nv_bfloat16 l = __float2bfloat16(v - __bfloat162float(h));
        const size_t o = (size_t)(c0 + i) * R + r0 + tx;
        dhi[o] = h; dlo[o] = l;
    }
}

__global__ void qkv_tsplit_k(const float* __restrict__ wq, const float* __restrict__ wk,
                             const float* __restrict__ wv)
{
    __shared__ float t[32][33];
    const int z = blockIdx.z;
    const int ts = z >> 4, h = z & 15;
    const float* w = ((ts == 0) ? wq : (ts == 1) ? wk : wv) + (size_t)h * 1024 * 64;
    const int d0 = blockIdx.x * 32, k0 = blockIdx.y * 32;
    const int tx = threadIdx.x, ty = threadIdx.y;
    #pragma unroll
    for (int i = ty; i < 32; i += 8)
        t[i][tx] = w[(size_t)(k0 + i) * 64 + d0 + tx];
    __syncthreads();
    #pragma unroll
    for (int i = ty; i < 32; i += 8) {
        const float v = t[tx][i];
        const __nv_bfloat16 hh = __float2bfloat16(v);
        const __nv_bfloat16 ll = __float2bfloat16(v - __bfloat162float(hh));
        const size_t o = (size_t)(ts * 1024 + h * 64 + d0 + i) * 1024 + k0 + tx;
        g_wqkvhi[o] = hh; g_wqkvlo[o] = ll;
    }
}

__global__ void bias_pack_k(const float* __restrict__ bq, const float* __restrict__ bk,
                            const float* __restrict__ bv)
{
    const int n = blockIdx.x * 256 + threadIdx.x;
    if (n < 3072) {
        const int t = n >> 10, rem = n & 1023;
        g_bqkv[n] = ((t == 0) ? bq : (t == 1) ? bk : bv)[rem];
    }
}

__global__ void split_k(const float* __restrict__ src,
                        __nv_bfloat16* __restrict__ dhi, __nv_bfloat16* __restrict__ dlo)
{
    const int i = blockIdx.x * 256 + threadIdx.x;
    const float v = src[i];
    const __nv_bfloat16 h = __float2bfloat16(v);
    dhi[i] = h;
    dlo[i] = __float2bfloat16(v - __bfloat162float(h));
}

// =================================================================================
// cp.async bf16x2-split GEMM: CTA tile 256x128, 512 threads, 16 warps of 64x32,
// k64 chunks, 2-stage pipeline (1 barrier per k64).
// mode 0: Cf = acc + bias (+res).  mode 1: Chi/Clo = acc + bias (relu opt).
// mode 2 (QKV): col<1024 -> Cf (fp32 Q); 1024..2047 -> Khi/Klo; 2048.. -> Vhi/Vlo.
// =================================================================================
__global__ void __launch_bounds__(512) gemm_cp(
    const __nv_bfloat16* __restrict__ Ahi, const __nv_bfloat16* __restrict__ Alo,
    const __nv_bfloat16* __restrict__ Bhi, const __nv_bfloat16* __restrict__ Blo,
    const float* __restrict__ bias, const float* __restrict__ res,
    float* __restrict__ Cf,
    __nv_bfloat16* __restrict__ Chi, __nv_bfloat16* __restrict__ Clo,
    __nv_bfloat16* __restrict__ Khi, __nv_bfloat16* __restrict__ Klo,
    __nv_bfloat16* __restrict__ Vhi, __nv_bfloat16* __restrict__ Vlo,
    int M, int N, int K, int relu, int mode)
{
    extern __shared__ __align__(128) char sm[];
    const uint32_t sbase = smem_u32(sm);

    const int tid  = threadIdx.x;
    const int wid  = tid >> 5;
    const int lane = tid & 31;
    const int bm = blockIdx.y * 256;
    const int bn = blockIdx.x * 128;
    const int warp_m = wid & 3;        // 4 x 64 rows
    const int warp_n = wid >> 2;       // 4 x 32 cols

    // loader: thread -> row r0 (A also r0+128), 16B chunks ch and ch+4 within 128B row
    const int r0 = tid >> 2;
    const int ch = tid & 3;
    const __nv_bfloat16* pAh = Ahi + (size_t)(bm + r0) * K + ch * 8;
    const __nv_bfloat16* pAl = Alo + (size_t)(bm + r0) * K + ch * 8;
    const __nv_bfloat16* pBh = Bhi + (size_t)(bn + r0) * K + ch * 8;
    const __nv_bfloat16* pBl = Blo + (size_t)(bn + r0) * K + ch * 8;
    const size_t arow2 = (size_t)128 * K;
    const uint32_t sA0 = (uint32_t)(r0 * ROWB + ch * 16);
    const uint32_t sA1 = sA0 + 128 * ROWB;

#define GEMM_ISSUE(dbuf, k0) do { \
    CP16((dbuf) + OFF_AHI + sA0,      pAh + (k0)); \
    CP16((dbuf) + OFF_AHI + sA0 + 64, pAh + (k0) + 32); \
    CP16((dbuf) + OFF_AHI + sA1,      pAh + (k0) + arow2); \
    CP16((dbuf) + OFF_AHI + sA1 + 64, pAh + (k0) + arow2 + 32); \
    CP16((dbuf) + OFF_ALO + sA0,      pAl + (k0)); \
    CP16((dbuf) + OFF_ALO + sA0 + 64, pAl + (k0) + 32); \
    CP16((dbuf) + OFF_ALO + sA1,      pAl + (k0) + arow2); \
    CP16((dbuf) + OFF_ALO + sA1 + 64, pAl + (k0) + arow2 + 32); \
    CP16((dbuf) + OFF_BHI + sA0,      pBh + (k0)); \
    CP16((dbuf) + OFF_BHI + sA0 + 64, pBh + (k0) + 32); \
    CP16((dbuf) + OFF_BLO + sA0,      pBl + (k0)); \
    CP16((dbuf) + OFF_BLO + sA0 + 64, pBl + (k0) + 32); \
} while (0)

    float acc[4][4][4];
    #pragma unroll
    for (int i = 0; i < 4; i++)
        #pragma unroll
        for (int j = 0; j < 4; j++)
            #pragma unroll
            for (int q = 0; q < 4; q++) acc[i][j][q] = 0.f;

    const int NCH = K >> 6;

    GEMM_ISSUE(sbase, 0); CP_COMMIT();

    for (int c = 0; c < NCH; c++) {
        CP_WAIT(0);
        __syncthreads();
        if (c + 1 < NCH) {
            GEMM_ISSUE(sbase + (uint32_t)((c + 1) & 1) * BUF_B, (c + 1) * 64);
            CP_COMMIT();
        }
        const uint32_t buf = sbase + (uint32_t)(c & 1) * BUF_B;

        #pragma unroll
        for (int ks = 0; ks < 4; ks++) {
            const int arow = warp_m * 64 + (lane & 15);
            const int acol = ks * 16 + (lane >> 4) * 8;
            const int nrow = warp_n * 32 + ((lane >> 4) << 3) + (lane & 7);
            const int bcol = ks * 16 + ((lane >> 3) & 1) * 8;

            // pass 1: hi x hi
            uint32_t a_hi[4][4], b_hi[2][4];
            #pragma unroll
            for (int im = 0; im < 4; im++)
                ldsm4(a_hi[im], buf + OFF_AHI + (uint32_t)((arow + im * 16) * ROWB + acol * 2));
            #pragma unroll
            for (int jb = 0; jb < 2; jb++)
                ldsm4(b_hi[jb], buf + OFF_BHI + (uint32_t)((nrow + jb * 16) * ROWB + bcol * 2));
            #pragma unroll
            for (int im = 0; im < 4; im++)
                #pragma unroll
                for (int jn = 0; jn < 4; jn++) {
                    const int jb = jn >> 1, sl = (jn & 1) * 2;
                    mma_bf16(acc[im][jn], a_hi[im], b_hi[jb][sl], b_hi[jb][sl + 1]);
                }
            // pass 2: hi x lo
            {
                uint32_t b_lo[2][4];
                #pragma unroll
                for (int jb = 0; jb < 2; jb++)
                    ldsm4(b_lo[jb], buf + OFF_BLO + (uint32_t)((nrow + jb * 16) * ROWB + bcol * 2));
                #pragma unroll
                for (int im = 0; im < 4; im++)
                    #pragma unroll
                    for (int jn = 0; jn < 4; jn++) {
                        const int jb = jn >> 1, sl = (jn & 1) * 2;
                        mma_bf16(acc[im][jn], a_hi[im], b_lo[jb][sl], b_lo[jb][sl + 1]);
                    }
            }
            // pass 3: lo x hi
            {
                uint32_t a_lo[4][4];
                #pragma unroll
                for (int im = 0; im < 4; im++)
                    ldsm4(a_lo[im], buf + OFF_ALO + (uint32_t)((arow + im * 16) * ROWB + acol * 2));
                #pragma unroll
                for (int im = 0; im < 4; im++)
                    #pragma unroll
                    for (int jn = 0; jn < 4; jn++) {
                        const int jb = jn >> 1, sl = (jn & 1) * 2;
                        mma_bf16(acc[im][jn], a_lo[im], b_hi[jb][sl], b_hi[jb][sl + 1]);
                    }
            }
        }
    }

    // ---- epilogue ----
    const int row0 = bm + warp_m * 64 + (lane >> 2);
    const int col0 = bn + warp_n * 32 + (lane & 3) * 2;
    const int sel = bn >> 10;       // mode 2 routing (CTA-uniform)
    #pragma unroll
    for (int im = 0; im < 4; im++) {
        #pragma unroll
        for (int half = 0; half < 2; half++) {
            const int r = row0 + im * 16 + half * 8;
            #pragma unroll
            for (int jn = 0; jn < 4; jn++) {
                const int cc = col0 + jn * 8;
                float2 o;
                o.x = acc[im][jn][2 * half]     + bias[cc];
                o.y = acc[im][jn][2 * half + 1] + bias[cc + 1];
                if (mode == 0) {
                    if (res) {
                        const float2 rv = *(const float2*)(res + (size_t)r * N + cc);
                        o.x += rv.x; o.y += rv.y;
                    }
                    *(float2*)(Cf + (size_t)r * N + cc) = o;
                } else if (mode == 1) {
                    if (relu) { o.x = fmaxf(o.x, 0.f); o.y = fmaxf(o.y, 0.f); }
                    uint32_t hv, lv;
                    split2(o.x, o.y, hv, lv);
                    *(uint32_t*)(Chi + (size_t)r * N + cc) = hv;
                    *(uint32_t*)(Clo + (size_t)r * N + cc) = lv;
                } else {
                    const int lc = cc - (sel << 10);
                    if (sel == 0) {
                        *(float2*)(Cf + (size_t)r * 1024 + lc) = o;
                    } else {
                        uint32_t hv, lv;
                        split2(o.x, o.y, hv, lv);
                        __nv_bfloat16* dh = (sel == 1) ? Khi : Vhi;
                        __nv_bfloat16* dl = (sel == 1) ? Klo : Vlo;
                        *(uint32_t*)(dh + (size_t)r * 1024 + lc) = hv;
                        *(uint32_t*)(dl + (size_t)r * 1024 + lc) = lv;
                    }
                }
            }
        }
    }
#undef GEMM_ISSUE
}

// =================================================================================
// Tensor-core flash attention; KV loaded pre-split via cp.async double buffer.
// =================================================================================
__global__ void __launch_bounds__(256) attn_mma_k()
{
    extern __shared__ __align__(128) char asmem[];
    const uint32_t sbase = smem_u32(asmem);
    const int tid  = threadIdx.x;
    const int wid  = tid >> 5;
    const int lane = tid & 31;
    const int bhid = blockIdx.y;
    const int bb = bhid >> 4, hh = bhid & 15;
    const int qbase = blockIdx.x * 128;
    const size_t kvrow0 = (size_t)bb * 1024;
    const int hcol = hh * 64;

    // ---- stage Q (scaled) and gather fragments ----
    float* Qf = (float*)asmem;
    for (int i = tid; i < 128 * 64; i += 256) {
        const int r = i >> 6, c = i & 63;
        Qf[r * 68 + c] = g_q[(kvrow0 + qbase + r) * 1024 + hcol + c] * 0.125f;
    }
    __syncthreads();

    uint32_t qhi[4][4], qlo[4][4];
    {
        const int r1 = wid * 16 + (lane >> 2);
        const int c0 = (lane & 3) * 2;
        #pragma unroll
        for (int t = 0; t < 4; t++)
            #pragma unroll
            for (int q = 0; q < 4; q++) {
                const int rr = r1 + (q & 1) * 8;
                const int cc = t * 16 + c0 + (q >> 1) * 8;
                split2(Qf[rr * 68 + cc], Qf[rr * 68 + cc + 1], qhi[t][q], qlo[t][q]);
            }
    }
    __syncthreads();

#define ATTN_ISSUE(dbuf, t) do { \
    _Pragma("unroll") \
    for (int u = 0; u < 2; u++) { \
        const int id = tid + u * 256; \
        const int row = id >> 3, c8 = id & 7; \
        const uint32_t off = (uint32_t)(row * AROWB + c8 * 16); \
        const size_t gl = (kvrow0 + (t) * 64 + row) * 1024 + hcol + c8 * 8; \
        CP16((dbuf) + AKHI + off, g_khi + gl); \
        CP16((dbuf) + AKLO + off, g_klo + gl); \
        CP16((dbuf) + AVHI + off, g_vhi + gl); \
        CP16((dbuf) + AVLO + off, g_vlo + gl); \
    } \
} while (0)

    float oacc[8][4];
    #pragma unroll
    for (int j = 0; j < 8; j++)
        #pragma unroll
        for (int q = 0; q < 4; q++) oacc[j][q] = 0.f;
    float m0 = -1e30f, m1 = -1e30f, l0 = 0.f, l1 = 0.f;

    ATTN_ISSUE(sbase, 0); CP_COMMIT();

    for (int t = 0; t < 16; t++) {
        CP_WAIT(0);
        __syncthreads();
        if (t + 1 < 16) {
            ATTN_ISSUE(sbase + (uint32_t)((t + 1) & 1) * ABUF, t + 1);
            CP_COMMIT();
        }
        const uint32_t bufu = sbase + (uint32_t)(t & 1) * ABUF;

        // ---- QK^T scores ----
        float s[8][4];
        #pragma unroll
        for (int j = 0; j < 8; j++)
            #pragma unroll
            for (int q = 0; q < 4; q++) s[j][q] = 0.f;

        #pragma unroll
        for (int ks = 0; ks < 4; ks++) {
            uint32_t kh[4][4], kl[4][4];
            const int nro = ((lane >> 4) << 3) + (lane & 7);
            const int kco = ks * 16 + ((lane >> 3) & 1) * 8;
            #pragma unroll
            for (int g = 0; g < 4; g++) {
                const uint32_t ad = bufu + (uint32_t)((g * 16 + nro) * AROWB + kco * 2);
                ldsm4(kh[g], ad + AKHI);
                ldsm4(kl[g], ad + AKLO);
            }
            #pragma unroll
            for (int g = 0; g < 4; g++) {
                mma_bf16(s[2 * g],     qhi[ks], kh[g][0], kh[g][1]);
                mma_bf16(s[2 * g + 1], qhi[ks], kh[g][2], kh[g][3]);
            }
            #pragma unroll
            for (int g = 0; g < 4; g++) {
                mma_bf16(s[2 * g],     qhi[ks], kl[g][0], kl[g][1]);
                mma_bf16(s[2 * g + 1], qhi[ks], kl[g][2], kl[g][3]);
            }
            #pragma unroll
            for (int g = 0; g < 4; g++) {
                mma_bf16(s[2 * g],     qlo[ks], kh[g][0], kh[g][1]);
                mma_bf16(s[2 * g + 1], qlo[ks], kh[g][2], kh[g][3]);
            }
        }

        // ---- online softmax ----
        float mx0 = s[0][0], mx1 = s[0][2];
        #pragma unroll
        for (int j = 0; j < 8; j++) {
            mx0 = fmaxf(mx0, fmaxf(s[j][0], s[j][1]));
            mx1 = fmaxf(mx1, fmaxf(s[j][2], s[j][3]));
        }
        mx0 = fmaxf(mx0, __shfl_xor_sync(0xFFFFFFFF, mx0, 1));
        mx0 = fmaxf(mx0, __shfl_xor_sync(0xFFFFFFFF, mx0, 2));
        mx1 = fmaxf(mx1, __shfl_xor_sync(0xFFFFFFFF, mx1, 1));
        mx1 = fmaxf(mx1, __shfl_xor_sync(0xFFFFFFFF, mx1, 2));
        const float nm0 = fmaxf(m0, mx0), nm1 = fmaxf(m1, mx1);
        const float sc0 = __expf(m0 - nm0), sc1 = __expf(m1 - nm1);
        m0 = nm0; m1 = nm1;
        l0 *= sc0; l1 *= sc1;
        #pragma unroll
        for (int j = 0; j < 8; j++) {
            oacc[j][0] *= sc0; oacc[j][1] *= sc0;
            oacc[j][2] *= sc1; oacc[j][3] *= sc1;
        }

        uint32_t aP[4][4];
        #pragma unroll
        for (int j = 0; j < 8; j++) {
            const float p0 = __expf(s[j][0] - m0);
            const float p1 = __expf(s[j][1] - m0);
            const float p2 = __expf(s[j][2] - m1);
            const float p3 = __expf(s[j][3] - m1);
            l0 += p0 + p1;
            l1 += p2 + p3;
            const int kt = j >> 1;
            if ((j & 1) == 0) { aP[kt][0] = packbf(p0, p1); aP[kt][1] = packbf(p2, p3); }
            else              { aP[kt][2] = packbf(p0, p1); aP[kt][3] = packbf(p2, p3); }
        }

        // ---- P·V ----
        #pragma unroll
        for (int ks = 0; ks < 4; ks++) {
            uint32_t vh[4][4], vl[4][4];
            const int kro = ks * 16 + ((lane >> 3) & 1) * 8 + (lane & 7);
            const int dco = ((lane >> 4) & 1) * 8;
            #pragma unroll
            for (int g = 0; g < 4; g++) {
                const uint32_t ad = bufu + (uint32_t)(kro * AROWB + (g * 16 + dco) * 2);
                ldsm4t(vh[g], ad + AVHI);
                ldsm4t(vl[g], ad + AVLO);
            }
            #pragma unroll
            for (int g = 0; g < 4; g++) {
                mma_bf16(oacc[2 * g],     aP[ks], vh[g][0], vh[g][1]);
                mma_bf16(oacc[2 * g + 1], aP[ks], vh[g][2], vh[g][3]);
            }
            #pragma unroll
            for (int g = 0; g < 4; g++) {
                mma_bf16(oacc[2 * g],     aP[ks], vl[g][0], vl[g][1]);
                mma_bf16(oacc[2 * g + 1], aP[ks], vl[g][2], vl[g][3]);
            }
        }
    }

    l0 += __shfl_xor_sync(0xFFFFFFFF, l0, 1);
    l0 += __shfl_xor_sync(0xFFFFFFFF, l0, 2);
    l1 += __shfl_xor_sync(0xFFFFFFFF, l1, 1);
    l1 += __shfl_xor_sync(0xFFFFFFFF, l1, 2);
    const float inv0 = 1.f / l0, inv1 = 1.f / l1;

    const int r1 = qbase + wid * 16 + (lane >> 2);
    const int c0 = (lane & 3) * 2;
    const size_t o1 = (kvrow0 + r1) * 1024 + hcol;
    const size_t o2 = o1 + 8 * 1024;
    #pragma unroll
    for (int j = 0; j < 8; j++) {
        const int cc = j * 8 + c0;
        uint32_t hv, lv;
        split2(oacc[j][0] * inv0, oacc[j][1] * inv0, hv, lv);
        *(uint32_t*)(g_ahi + o1 + cc) = hv;
        *(uint32_t*)(g_alo + o1 + cc) = lv;
        split2(oacc[j][2] * inv1, oacc[j][3] * inv1, hv, lv);
        *(uint32_t*)(g_ahi + o2 + cc) = hv;
        *(uint32_t*)(g_alo + o2 + cc) = lv;
    }
#undef ATTN_ISSUE
}

// =================================================================================
// LayerNorm: out fp32 + optional bf16 hi/lo
// =================================================================================
__global__ void __launch_bounds__(256) layernorm_k(
    const float* __restrict__ in, const float* __restrict__ gamma,
    const float* __restrict__ beta, float* __restrict__ out,
    __nv_bfloat16* __restrict__ ohi, __nv_bfloat16* __restrict__ olo)
{
    __shared__ float red[256];
    const int row = blockIdx.x;
    const int tid = threadIdx.x;

    const float4 v = ((const float4*)(in + (size_t)row * 1024))[tid];
    float s = v.x + v.y + v.z + v.w;
    red[tid] = s;
    __syncthreads();
    #pragma unroll
    for (int off = 128; off > 0; off >>= 1) {
        if (tid < off) red[tid] += red[tid + off];
        __syncthreads();
    }
    const float mean = red[0] * (1.f / 1024.f);
    __syncthreads();

    const float d0 = v.x - mean, d1 = v.y - mean, d2 = v.z - mean, d3 = v.w - mean;
    s = d0 * d0 + d1 * d1 + d2 * d2 + d3 * d3;
    red[tid] = s;
    __syncthreads();
    #pragma unroll
    for (int off = 128; off > 0; off >>= 1) {
        if (tid < off) red[tid] += red[tid + off];
        __syncthreads();
    }
    const float var = red[0] * (1.f / 1024.f);
    const float inv = 1.f / (sqrtf(var) + LN_EPS);

    const float4 gv = ((const float4*)gamma)[tid];
    const float4 bv = ((const float4*)beta)[tid];
    float4 ov;
    ov.x = gv.x * d0 * inv + bv.x;
    ov.y = gv.y * d1 * inv + bv.y;
    ov.z = gv.z * d2 * inv + bv.z;
    ov.w = gv.w * d3 * inv + bv.w;
    ((float4*)(out + (size_t)row * 1024))[tid] = ov;
    if (ohi) {
        uint32_t h0, l0_, h1, l1_;
        split2(ov.x, ov.y, h0, l0_);
        split2(ov.z, ov.w, h1, l1_);
        const size_t o = (size_t)row * 1024 + tid * 4;
        *(uint2*)(ohi + o) = make_uint2(h0, h1);
        *(uint2*)(olo + o) = make_uint2(l0_, l1_);
    }
}

// =================================================================================
// Launch
// =================================================================================
template <typename T>
static T* sym_addr(const void* symbol)
{
    void* p = nullptr;
    cudaGetSymbolAddress(&p, symbol);
    return (T*)p;
}

extern "C" void kernel_launch(void* const* d_in, const int* in_sizes, int n_in,
                              void* d_out, int out_size)
{
    const float* x     = (const float*)d_in[0];
    const float* wq    = (const float*)d_in[1];
    const float* bq    = (const float*)d_in[2];
    const float* wk    = (const float*)d_in[3];
    const float* bk    = (const float*)d_in[4];
    const float* wv    = (const float*)d_in[5];
    const float* bv    = (const float*)d_in[6];
    const float* wo_w  = (const float*)d_in[7];
    const float* wo_b  = (const float*)d_in[8];
    const float* g1    = (const float*)d_in[9];
    const float* b1    = (const float*)d_in[10];
    const float* ff1_w = (const float*)d_in[11];
    const float* ff1_b = (const float*)d_in[12];
    const float* ff2_w = (const float*)d_in[13];
    const float* ff2_b = (const float*)d_in[14];
    const float* g2    = (const float*)d_in[15];
    const float* b2    = (const float*)d_in[16];

    float* q    = sym_addr<float>(g_q);
    float* tmp  = sym_addr<float>(g_tmp);
    float* h    = sym_addr<float>(g_h);
    float* bqkv = sym_addr<float>(g_bqkv);
    __nv_bfloat16* khi = sym_addr<__nv_bfloat16>(g_khi);
    __nv_bfloat16* klo = sym_addr<__nv_bfloat16>(g_klo);
    __nv_bfloat16* vhi = sym_addr<__nv_bfloat16>(g_vhi);
    __nv_bfloat16* vlo = sym_addr<__nv_bfloat16>(g_vlo);
    __nv_bfloat16* xhi = sym_addr<__nv_bfloat16>(g_xhi);
    __nv_bfloat16* xlo = sym_addr<__nv_bfloat16>(g_xlo);
    __nv_bfloat16* ahi = sym_addr<__nv_bfloat16>(g_ahi);
    __nv_bfloat16* alo = sym_addr<__nv_bfloat16>(g_alo);
    __nv_bfloat16* hhi = sym_addr<__nv_bfloat16>(g_hhi);
    __nv_bfloat16* hlo = sym_addr<__nv_bfloat16>(g_hlo);
    __nv_bfloat16* fhi = sym_addr<__nv_bfloat16>(g_fhi);
    __nv_bfloat16* flo = sym_addr<__nv_bfloat16>(g_flo);
    __nv_bfloat16* wqkvhi = sym_addr<__nv_bfloat16>(g_wqkvhi);
    __nv_bfloat16* wqkvlo = sym_addr<__nv_bfloat16>(g_wqkvlo);
    __nv_bfloat16* wohi = sym_addr<__nv_bfloat16>(g_wohi);
    __nv_bfloat16* wolo = sym_addr<__nv_bfloat16>(g_wolo);
    __nv_bfloat16* w1hi = sym_addr<__nv_bfloat16>(g_w1hi);
    __nv_bfloat16* w1lo = sym_addr<__nv_bfloat16>(g_w1lo);
    __nv_bfloat16* w2hi = sym_addr<__nv_bfloat16>(g_w2hi);
    __nv_bfloat16* w2lo = sym_addr<__nv_bfloat16>(g_w2lo);

    cudaFuncSetAttribute(gemm_cp, cudaFuncAttributeMaxDynamicSharedMemorySize, GSMEM);
    cudaFuncSetAttribute(attn_mma_k, cudaFuncAttributeMaxDynamicSharedMemorySize, ASMEM);

    dim3 tb(32, 8);
    // packs needed for QKV first (launches 1-4), QKV GEMM at #5, attn at #6
    qkv_tsplit_k<<<dim3(2, 32, 48), tb>>>(wq, wk, wv);
    bias_pack_k<<<12, 256>>>(bq, bk, bv);
    split_k<<<(ROWS * DM) / 256, 256>>>(x, xhi, xlo);
    tsplit_k<<<dim3(32, 32), tb>>>(wo_w, wohi, wolo, DM, DM);

    // 1) fused QKV projection -> Q fp32, K/V bf16 hi/lo          [launch #5]
    gemm_cp<<<dim3(24, 16), 512, GSMEM>>>(xhi, xlo, wqkvhi, wqkvlo, bqkv, nullptr,
                                          q, nullptr, nullptr, khi, klo, vhi, vlo,
                                          ROWS, 3 * DM, DM, 0, 2);
    // 2) attention -> ahi/alo                                     [launch #6]
    attn_mma_k<<<dim3(SEQ / 128, B_SZ * NH), 256, ASMEM>>>();

    // remaining weight packs (dep-free until FF GEMMs)
    tsplit_k<<<dim3(64, 32), tb>>>(ff1_w, w1hi, w1lo, DM, DFF);
    tsplit_k<<<dim3(32, 64), tb>>>(ff2_w, w2hi, w2lo, DFF, DM);

    // 3) O-proj + residual(x) -> tmp fp32
    gemm_cp<<<dim3(8, 16), 512, GSMEM>>>(ahi, alo, wohi, wolo, wo_b, x,
                                         tmp, nullptr, nullptr, nullptr, nullptr, nullptr, nullptr,
                                         ROWS, DM, DM, 0, 0);
    // 4) LN1 -> h fp32 + hhi/hlo
    layernorm_k<<<ROWS, 256>>>(tmp, g1, b1, h, hhi, hlo);
    // 5) FF1 + ReLU -> fhi/flo
    gemm_cp<<<dim3(16, 16), 512, GSMEM>>>(hhi, hlo, w1hi, w1lo, ff1_b, nullptr,
                                          nullptr, fhi, flo, nullptr, nullptr, nullptr, nullptr,
                                          ROWS, DFF, DM, 1, 1);
    // 6) FF2 + residual(h) -> tmp fp32
    gemm_cp<<<dim3(8, 16), 512, GSMEM>>>(fhi, flo, w2hi, w2lo, ff2_b, h,
                                         tmp, nullptr, nullptr, nullptr, nullptr, nullptr, nullptr,
                                         ROWS, DM, DFF, 0, 0);
    // 7) LN2 -> output
    layernorm_k<<<ROWS, 256>>>(tmp, g2, b2, (float*)d_out, nullptr, nullptr);
}

// round 10
// speedup vs baseline: 1.1262x; 1.1262x over previous
#include <cuda_runtime.h>
#include <cuda_bf16.h>
#include <cuda_fp16.h>
#include <math.h>
#include <cstdint>

#define B_SZ   4
#define SEQ    1024
#define DM     1024
#define NH     16
#define DFF    2048
#define ROWS   (B_SZ*SEQ)        // 4096
#define LN_EPS 1e-5f

// GEMM smem: CTA tile 256x128, chunk k64. Row stride 144B (128B data + 16B pad).
#define ROWB      144
#define OFF_AHI   0
#define OFF_ALO   36864
#define OFF_BHI   73728
#define OFF_BLO   92160
#define BUF_B     110592
#define GSMEM     (2*BUF_B)      // 221184

// Attention smem
#define AROWB     144
#define ATILE     (64*AROWB)
#define AKHI      0
#define AKLO      (ATILE)
#define AVHI      (2*ATILE)
#define AVLO      (3*ATILE)
#define ABUF      (4*ATILE)
#define ASMEM     (2*ABUF)

// ---------------- scratch (device globals) ----------------
__device__ float g_q[ROWS*DM];
__device__ float g_tmp[ROWS*DM];
__device__ float g_h[ROWS*DM];
__device__ float g_bqkv[3*DM];
__device__ __nv_bfloat16 g_khi[ROWS*DM],   g_klo[ROWS*DM];
__device__ __nv_bfloat16 g_vhi[ROWS*DM],   g_vlo[ROWS*DM];
__device__ __nv_bfloat16 g_xhi[ROWS*DM],   g_xlo[ROWS*DM];
__device__ __nv_bfloat16 g_ahi[ROWS*DM],   g_alo[ROWS*DM];        // attention out (bf16)
__device__ __half        g_hhi[ROWS*DM],   g_hlo[ROWS*DM];        // LN1 out (fp16)
__device__ __half        g_fhi[ROWS*DFF],  g_flo[ROWS*DFF];       // FF1 out (fp16)
__device__ __nv_bfloat16 g_wqkvhi[3*DM*DM], g_wqkvlo[3*DM*DM];
__device__ __nv_bfloat16 g_wohi[DM*DM],     g_wolo[DM*DM];
__device__ __half        g_w1h[DFF*DM];                           // fp16 hi only
__device__ __half        g_w2h[DM*DFF];                           // fp16 hi only

// =================================================================================
// helpers
// =================================================================================
__device__ __forceinline__ uint32_t smem_u32(const void* p) {
    uint32_t a;
    asm("{ .reg .u64 t; cvta.to.shared.u64 t, %1; cvt.u32.u64 %0, t; }" : "=r"(a) : "l"(p));
    return a;
}
__device__ __forceinline__ void ldsm4(uint32_t* r, uint32_t addr) {
    asm volatile("ldmatrix.sync.aligned.m8n8.x4.shared.b16 {%0,%1,%2,%3}, [%4];"
                 : "=r"(r[0]), "=r"(r[1]), "=r"(r[2]), "=r"(r[3]) : "r"(addr));
}
__device__ __forceinline__ void ldsm4t(uint32_t* r, uint32_t addr) {
    asm volatile("ldmatrix.sync.aligned.m8n8.x4.trans.shared.b16 {%0,%1,%2,%3}, [%4];"
                 : "=r"(r[0]), "=r"(r[1]), "=r"(r[2]), "=r"(r[3]) : "r"(addr));
}
__device__ __forceinline__ void mma_bf16(float* d, const uint32_t* a, uint32_t b0, uint32_t b1) {
    asm volatile("mma.sync.aligned.m16n8k16.row.col.f32.bf16.bf16.f32 "
                 "{%0,%1,%2,%3}, {%4,%5,%6,%7}, {%8,%9}, {%0,%1,%2,%3};"
                 : "+f"(d[0]), "+f"(d[1]), "+f"(d[2]), "+f"(d[3])
                 : "r"(a[0]), "r"(a[1]), "r"(a[2]), "r"(a[3]), "r"(b0), "r"(b1));
}
__device__ __forceinline__ void mma_f16(float* d, const uint32_t* a, uint32_t b0, uint32_t b1) {
    asm volatile("mma.sync.aligned.m16n8k16.row.col.f32.f16.f16.f32 "
                 "{%0,%1,%2,%3}, {%4,%5,%6,%7}, {%8,%9}, {%0,%1,%2,%3};"
                 : "+f"(d[0]), "+f"(d[1]), "+f"(d[2]), "+f"(d[3])
                 : "r"(a[0]), "r"(a[1]), "r"(a[2]), "r"(a[3]), "r"(b0), "r"(b1));
}
#define CP16(dst, src) asm volatile("cp.async.cg.shared.global [%0], [%1], 16;" :: "r"(dst), "l"(src))
#define CP_COMMIT()    asm volatile("cp.async.commit_group;" ::: "memory")
#define CP_WAIT(n)     asm volatile("cp.async.wait_group %0;" :: "n"(n) : "memory")

__device__ __forceinline__ void split2(float a, float b, uint32_t& hi, uint32_t& lo) {
    __nv_bfloat16 ah = __float2bfloat16(a);
    __nv_bfloat16 bh = __float2bfloat16(b);
    __nv_bfloat16 al = __float2bfloat16(a - __bfloat162float(ah));
    __nv_bfloat16 bl = __float2bfloat16(b - __bfloat162float(bh));
    __nv_bfloat162 h2; h2.x = ah; h2.y = bh;
    __nv_bfloat162 l2; l2.x = al; l2.y = bl;
    hi = *reinterpret_cast<uint32_t*>(&h2);
    lo = *reinterpret_cast<uint32_t*>(&l2);
}
__device__ __forceinline__ void split2h(float a, float b, uint32_t& hi, uint32_t& lo) {
    __half ah = __float2half_rn(a);
    __half bh = __float2half_rn(b);
    __half al = __float2half_rn(a - __half2float(ah));
    __half bl = __float2half_rn(b - __half2float(bh));
    __half2 h2; h2.x = ah; h2.y = bh;
    __half2 l2; l2.x = al; l2.y = bl;
    hi = *reinterpret_cast<uint32_t*>(&h2);
    lo = *reinterpret_cast<uint32_t*>(&l2);
}
__device__ __forceinline__ uint32_t packbf(float a, float b) {
    __nv_bfloat162 t; t.x = __float2bfloat16(a); t.y = __float2bfloat16(b);
    return *reinterpret_cast<uint32_t*>(&t);
}

// =================================================================================
// weight packing
// =================================================================================
__global__ void tsplit_k(const float* __restrict__ src,
                         __nv_bfloat16* __restrict__ dhi, __nv_bfloat16* __restrict__ dlo,
                         int R, int C)
{
    __shared__ float t[32][33];
    const int c0 = blockIdx.x * 32, r0 = blockIdx.y * 32;
    const int tx = threadIdx.x, ty = threadIdx.y;
    #pragma unroll
    for (int i = ty; i < 32; i += 8)
        t[i][tx] = src[(size_t)(r0 + i) * C + c0 + tx];
    __syncthreads();
    #pragma unroll
    for (int i = ty; i < 32; i += 8) {
        const float v = t[tx][i];
        const __nv_bfloat16 h = __float2bfloat16(v);
        const __nv_bfloat16 l = __float2bfloat16(v - __bfloat162float(h));
        const size_t o = (size_t)(c0 + i) * R + r0 + tx;
        dhi[o] = h; dlo[o] = l;
    }
}

// transpose + fp16 (hi only)
__global__ void tsplit_f16_k(const float* __restrict__ src,
                             __half* __restrict__ dhi, int R, int C)
{
    __shared__ float t[32][33];
    const int c0 = blockIdx.x * 32, r0 = blockIdx.y * 32;
    const int tx = threadIdx.x, ty = threadIdx.y;
    #pragma unroll
    for (int i = ty; i < 32; i += 8)
        t[i][tx] = src[(size_t)(r0 + i) * C + c0 + tx];
    __syncthreads();
    #pragma unroll
    for (int i = ty; i < 32; i += 8)
        dhi[(size_t)(c0 + i) * R + r0 + tx] = __float2half_rn(t[tx][i]);
}

__global__ void qkv_tsplit_k(const float* __restrict__ wq, const float* __restrict__ wk,
                             const float* __restrict__ wv)
{
    __shared__ float t[32][33];
    const int z = blockIdx.z;
    const int ts = z >> 4, h = z & 15;
    const float* w = ((ts == 0) ? wq : (ts == 1) ? wk : wv) + (size_t)h * 1024 * 64;
    const int d0 = blockIdx.x * 32, k0 = blockIdx.y * 32;
    const int tx = threadIdx.x, ty = threadIdx.y;
    #pragma unroll
    for (int i = ty; i < 32; i += 8)
        t[i][tx] = w[(size_t)(k0 + i) * 64 + d0 + tx];
    __syncthreads();
    #pragma unroll
    for (int i = ty; i < 32; i += 8) {
        const float v = t[tx][i];
        const __nv_bfloat16 hh = __float2bfloat16(v);
        const __nv_bfloat16 ll = __float2bfloat16(v - __bfloat162float(hh));
        const size_t o = (size_t)(ts * 1024 + h * 64 + d0 + i) * 1024 + k0 + tx;
        g_wqkvhi[o] = hh; g_wqkvlo[o] = ll;
    }
}

__global__ void bias_pack_k(const float* __restrict__ bq, const float* __restrict__ bk,
                            const float* __restrict__ bv)
{
    const int n = blockIdx.x * 256 + threadIdx.x;
    if (n < 3072) {
        const int t = n >> 10, rem = n & 1023;
        g_bqkv[n] = ((t == 0) ? bq : (t == 1) ? bk : bv)[rem];
    }
}

__global__ void split_k(const float* __restrict__ src,
                        __nv_bfloat16* __restrict__ dhi, __nv_bfloat16* __restrict__ dlo)
{
    const int i = blockIdx.x * 256 + threadIdx.x;
    const float v = src[i];
    const __nv_bfloat16 h = __float2bfloat16(v);
    dhi[i] = h;
    dlo[i] = __float2bfloat16(v - __bfloat162float(h));
}

// =================================================================================
// cp.async split GEMM: CTA 256x128, 512 threads, 16 warps 64x32, k64 2-stage.
// F16=0: bf16 3-pass (AhiBhi + AhiBlo + AloBhi).
// F16=1: fp16 2-pass (AhiBhi + AloBhi) — B_lo neither loaded nor used.
// mode 0: Cf = acc + bias (+res).  mode 1: Chi/Clo (2-byte) = acc + bias (relu opt).
// mode 2 (QKV): col<1024 -> Cf (fp32 Q); 1024..2047 -> Khi/Klo; 2048.. -> Vhi/Vlo.
// =================================================================================
template <int F16>
__global__ void __launch_bounds__(512) gemm_cp(
    const __nv_bfloat16* __restrict__ Ahi, const __nv_bfloat16* __restrict__ Alo,
    const __nv_bfloat16* __restrict__ Bhi, const __nv_bfloat16* __restrict__ Blo,
    const float* __restrict__ bias, const float* __restrict__ res,
    float* __restrict__ Cf,
    __nv_bfloat16* __restrict__ Chi, __nv_bfloat16* __restrict__ Clo,
    __nv_bfloat16* __restrict__ Khi, __nv_bfloat16* __restrict__ Klo,
    __nv_bfloat16* __restrict__ Vhi, __nv_bfloat16* __restrict__ Vlo,
    int M, int N, int K, int relu, int mode)
{
    extern __shared__ __align__(128) char sm[];
    const uint32_t sbase = smem_u32(sm);

    const int tid  = threadIdx.x;
    const int wid  = tid >> 5;
    const int lane = tid & 31;
    const int bm = blockIdx.y * 256;
    const int bn = blockIdx.x * 128;
    const int warp_m = wid & 3;
    const int warp_n = wid >> 2;

    const int r0 = tid >> 2;
    const int ch = tid & 3;
    const __nv_bfloat16* pAh = Ahi + (size_t)(bm + r0) * K + ch * 8;
    const __nv_bfloat16* pAl = Alo + (size_t)(bm + r0) * K + ch * 8;
    const __nv_bfloat16* pBh = Bhi + (size_t)(bn + r0) * K + ch * 8;
    const __nv_bfloat16* pBl = F16 ? nullptr : (Blo + (size_t)(bn + r0) * K + ch * 8);
    const size_t arow2 = (size_t)128 * K;
    const uint32_t sA0 = (uint32_t)(r0 * ROWB + ch * 16);
    const uint32_t sA1 = sA0 + 128 * ROWB;

    auto issue = [&](uint32_t dbuf, int k0) {
        CP16(dbuf + OFF_AHI + sA0,      pAh + k0);
        CP16(dbuf + OFF_AHI + sA0 + 64, pAh + k0 + 32);
        CP16(dbuf + OFF_AHI + sA1,      pAh + k0 + arow2);
        CP16(dbuf + OFF_AHI + sA1 + 64, pAh + k0 + arow2 + 32);
        CP16(dbuf + OFF_ALO + sA0,      pAl + k0);
        CP16(dbuf + OFF_ALO + sA0 + 64, pAl + k0 + 32);
        CP16(dbuf + OFF_ALO + sA1,      pAl + k0 + arow2);
        CP16(dbuf + OFF_ALO + sA1 + 64, pAl + k0 + arow2 + 32);
        CP16(dbuf + OFF_BHI + sA0,      pBh + k0);
        CP16(dbuf + OFF_BHI + sA0 + 64, pBh + k0 + 32);
        if (!F16) {
            CP16(dbuf + OFF_BLO + sA0,      pBl + k0);
            CP16(dbuf + OFF_BLO + sA0 + 64, pBl + k0 + 32);
        }
    };

    float acc[4][4][4];
    #pragma unroll
    for (int i = 0; i < 4; i++)
        #pragma unroll
        for (int j = 0; j < 4; j++)
            #pragma unroll
            for (int q = 0; q < 4; q++) acc[i][j][q] = 0.f;

    const int NCH = K >> 6;

    issue(sbase, 0); CP_COMMIT();

    for (int c = 0; c < NCH; c++) {
        CP_WAIT(0);
        __syncthreads();
        if (c + 1 < NCH) {
            issue(sbase + (uint32_t)((c + 1) & 1) * BUF_B, (c + 1) * 64);
            CP_COMMIT();
        }
        const uint32_t buf = sbase + (uint32_t)(c & 1) * BUF_B;

        #pragma unroll
        for (int ks = 0; ks < 4; ks++) {
            const int arow = warp_m * 64 + (lane & 15);
            const int acol = ks * 16 + (lane >> 4) * 8;
            const int nrow = warp_n * 32 + ((lane >> 4) << 3) + (lane & 7);
            const int bcol = ks * 16 + ((lane >> 3) & 1) * 8;

            // pass 1: hi x hi
            uint32_t a_hi[4][4], b_hi[2][4];
            #pragma unroll
            for (int im = 0; im < 4; im++)
                ldsm4(a_hi[im], buf + OFF_AHI + (uint32_t)((arow + im * 16) * ROWB + acol * 2));
            #pragma unroll
            for (int jb = 0; jb < 2; jb++)
                ldsm4(b_hi[jb], buf + OFF_BHI + (uint32_t)((nrow + jb * 16) * ROWB + bcol * 2));
            #pragma unroll
            for (int im = 0; im < 4; im++)
                #pragma unroll
                for (int jn = 0; jn < 4; jn++) {
                    const int jb = jn >> 1, sl = (jn & 1) * 2;
                    if (F16) mma_f16(acc[im][jn], a_hi[im], b_hi[jb][sl], b_hi[jb][sl + 1]);
                    else     mma_bf16(acc[im][jn], a_hi[im], b_hi[jb][sl], b_hi[jb][sl + 1]);
                }
            // pass 2 (bf16 only): hi x lo
            if (!F16) {
                uint32_t b_lo[2][4];
                #pragma unroll
                for (int jb = 0; jb < 2; jb++)
                    ldsm4(b_lo[jb], buf + OFF_BLO + (uint32_t)((nrow + jb * 16) * ROWB + bcol * 2));
                #pragma unroll
                for (int im = 0; im < 4; im++)
                    #pragma unroll
                    for (int jn = 0; jn < 4; jn++) {
                        const int jb = jn >> 1, sl = (jn & 1) * 2;
                        mma_bf16(acc[im][jn], a_hi[im], b_lo[jb][sl], b_lo[jb][sl + 1]);
                    }
            }
            // pass 3 (bf16) / pass 2 (fp16): lo x hi
            {
                uint32_t a_lo[4][4];
                #pragma unroll
                for (int im = 0; im < 4; im++)
                    ldsm4(a_lo[im], buf + OFF_ALO + (uint32_t)((arow + im * 16) * ROWB + acol * 2));
                #pragma unroll
                for (int im = 0; im < 4; im++)
                    #pragma unroll
                    for (int jn = 0; jn < 4; jn++) {
                        const int jb = jn >> 1, sl = (jn & 1) * 2;
                        if (F16) mma_f16(acc[im][jn], a_lo[im], b_hi[jb][sl], b_hi[jb][sl + 1]);
                        else     mma_bf16(acc[im][jn], a_lo[im], b_hi[jb][sl], b_hi[jb][sl + 1]);
                    }
            }
        }
    }

    // ---- epilogue ----
    const int row0 = bm + warp_m * 64 + (lane >> 2);
    const int col0 = bn + warp_n * 32 + (lane & 3) * 2;
    const int sel = bn >> 10;
    #pragma unroll
    for (int im = 0; im < 4; im++) {
        #pragma unroll
        for (int half = 0; half < 2; half++) {
            const int r = row0 + im * 16 + half * 8;
            #pragma unroll
            for (int jn = 0; jn < 4; jn++) {
                const int cc = col0 + jn * 8;
                float2 o;
                o.x = acc[im][jn][2 * half]     + bias[cc];
                o.y = acc[im][jn][2 * half + 1] + bias[cc + 1];
                if (mode == 0) {
                    if (res) {
                        const float2 rv = *(const float2*)(res + (size_t)r * N + cc);
                        o.x += rv.x; o.y += rv.y;
                    }
                    *(float2*)(Cf + (size_t)r * N + cc) = o;
                } else if (mode == 1) {
                    if (relu) { o.x = fmaxf(o.x, 0.f); o.y = fmaxf(o.y, 0.f); }
                    uint32_t hv, lv;
                    if (F16) split2h(o.x, o.y, hv, lv); else split2(o.x, o.y, hv, lv);
                    *(uint32_t*)(Chi + (size_t)r * N + cc) = hv;
                    *(uint32_t*)(Clo + (size_t)r * N + cc) = lv;
                } else {
                    const int lc = cc - (sel << 10);
                    if (sel == 0) {
                        *(float2*)(Cf + (size_t)r * 1024 + lc) = o;
                    } else {
                        uint32_t hv, lv;
                        split2(o.x, o.y, hv, lv);
                        __nv_bfloat16* dh = (sel == 1) ? Khi : Vhi;
                        __nv_bfloat16* dl = (sel == 1) ? Klo : Vlo;
                        *(uint32_t*)(dh + (size_t)r * 1024 + lc) = hv;
                        *(uint32_t*)(dl + (size_t)r * 1024 + lc) = lv;
                    }
                }
            }
        }
    }
}

// =================================================================================
// Tensor-core flash attention (unchanged)
// =================================================================================
__global__ void __launch_bounds__(256) attn_mma_k()
{
    extern __shared__ __align__(128) char asmem[];
    const uint32_t sbase = smem_u32(asmem);
    const int tid  = threadIdx.x;
    const int wid  = tid >> 5;
    const int lane = tid & 31;
    const int bhid = blockIdx.y;
    const int bb = bhid >> 4, hh = bhid & 15;
    const int qbase = blockIdx.x * 128;
    const size_t kvrow0 = (size_t)bb * 1024;
    const int hcol = hh * 64;

    float* Qf = (float*)asmem;
    for (int i = tid; i < 128 * 64; i += 256) {
        const int r = i >> 6, c = i & 63;
        Qf[r * 68 + c] = g_q[(kvrow0 + qbase + r) * 1024 + hcol + c] * 0.125f;
    }
    __syncthreads();

    uint32_t qhi[4][4], qlo[4][4];
    {
        const int r1 = wid * 16 + (lane >> 2);
        const int c0 = (lane & 3) * 2;
        #pragma unroll
        for (int t = 0; t < 4; t++)
            #pragma unroll
            for (int q = 0; q < 4; q++) {
                const int rr = r1 + (q & 1) * 8;
                const int cc = t * 16 + c0 + (q >> 1) * 8;
                split2(Qf[rr * 68 + cc], Qf[rr * 68 + cc + 1], qhi[t][q], qlo[t][q]);
            }
    }
    __syncthreads();

#define ATTN_ISSUE(dbuf, t) do { \
    _Pragma("unroll") \
    for (int u = 0; u < 2; u++) { \
        const int id = tid + u * 256; \
        const int row = id >> 3, c8 = id & 7; \
        const uint32_t off = (uint32_t)(row * AROWB + c8 * 16); \
        const size_t gl = (kvrow0 + (t) * 64 + row) * 1024 + hcol + c8 * 8; \
        CP16((dbuf) + AKHI + off, g_khi + gl); \
        CP16((dbuf) + AKLO + off, g_klo + gl); \
        CP16((dbuf) + AVHI + off, g_vhi + gl); \
        CP16((dbuf) + AVLO + off, g_vlo + gl); \
    } \
} while (0)

    float oacc[8][4];
    #pragma unroll
    for (int j = 0; j < 8; j++)
        #pragma unroll
        for (int q = 0; q < 4; q++) oacc[j][q] = 0.f;
    float m0 = -1e30f, m1 = -1e30f, l0 = 0.f, l1 = 0.f;

    ATTN_ISSUE(sbase, 0); CP_COMMIT();

    for (int t = 0; t < 16; t++) {
        CP_WAIT(0);
        __syncthreads();
        if (t + 1 < 16) {
            ATTN_ISSUE(sbase + (uint32_t)((t + 1) & 1) * ABUF, t + 1);
            CP_COMMIT();
        }
        const uint32_t bufu = sbase + (uint32_t)(t & 1) * ABUF;

        float s[8][4];
        #pragma unroll
        for (int j = 0; j < 8; j++)
            #pragma unroll
            for (int q = 0; q < 4; q++) s[j][q] = 0.f;

        #pragma unroll
        for (int ks = 0; ks < 4; ks++) {
            uint32_t kh[4][4], kl[4][4];
            const int nro = ((lane >> 4) << 3) + (lane & 7);
            const int kco = ks * 16 + ((lane >> 3) & 1) * 8;
            #pragma unroll
            for (int g = 0; g < 4; g++) {
                const uint32_t ad = bufu + (uint32_t)((g * 16 + nro) * AROWB + kco * 2);
                ldsm4(kh[g], ad + AKHI);
                ldsm4(kl[g], ad + AKLO);
            }
            #pragma unroll
            for (int g = 0; g < 4; g++) {
                mma_bf16(s[2 * g],     qhi[ks], kh[g][0], kh[g][1]);
                mma_bf16(s[2 * g + 1], qhi[ks], kh[g][2], kh[g][3]);
            }
            #pragma unroll
            for (int g = 0; g < 4; g++) {
                mma_bf16(s[2 * g],     qhi[ks], kl[g][0], kl[g][1]);
                mma_bf16(s[2 * g + 1], qhi[ks], kl[g][2], kl[g][3]);
            }
            #pragma unroll
            for (int g = 0; g < 4; g++) {
                mma_bf16(s[2 * g],     qlo[ks], kh[g][0], kh[g][1]);
                mma_bf16(s[2 * g + 1], qlo[ks], kh[g][2], kh[g][3]);
            }
        }

        float mx0 = s[0][0], mx1 = s[0][2];
        #pragma unroll
        for (int j = 0; j < 8; j++) {
            mx0 = fmaxf(mx0, fmaxf(s[j][0], s[j][1]));
            mx1 = fmaxf(mx1, fmaxf(s[j][2], s[j][3]));
        }
        mx0 = fmaxf(mx0, __shfl_xor_sync(0xFFFFFFFF, mx0, 1));
        mx0 = fmaxf(mx0, __shfl_xor_sync(0xFFFFFFFF, mx0, 2));
        mx1 = fmaxf(mx1, __shfl_xor_sync(0xFFFFFFFF, mx1, 1));
        mx1 = fmaxf(mx1, __shfl_xor_sync(0xFFFFFFFF, mx1, 2));
        const float nm0 = fmaxf(m0, mx0), nm1 = fmaxf(m1, mx1);
        const float sc0 = __expf(m0 - nm0), sc1 = __expf(m1 - nm1);
        m0 = nm0; m1 = nm1;
        l0 *= sc0; l1 *= sc1;
        #pragma unroll
        for (int j = 0; j < 8; j++) {
            oacc[j][0] *= sc0; oacc[j][1] *= sc0;
            oacc[j][2] *= sc1; oacc[j][3] *= sc1;
        }

        uint32_t aP[4][4];
        #pragma unroll
        for (int j = 0; j < 8; j++) {
            const float p0 = __expf(s[j][0] - m0);
            const float p1 = __expf(s[j][1] - m0);
            const float p2 = __expf(s[j][2] - m1);
            const float p3 = __expf(s[j][3] - m1);
            l0 += p0 + p1;
            l1 += p2 + p3;
            const int kt = j >> 1;
            if ((j & 1) == 0) { aP[kt][0] = packbf(p0, p1); aP[kt][1] = packbf(p2, p3); }
            else              { aP[kt][2] = packbf(p0, p1); aP[kt][3] = packbf(p2, p3); }
        }

        #pragma unroll
        for (int ks = 0; ks < 4; ks++) {
            uint32_t vh[4][4], vl[4][4];
            const int kro = ks * 16 + ((lane >> 3) & 1) * 8 + (lane & 7);
            const int dco = ((lane >> 4) & 1) * 8;
            #pragma unroll
            for (int g = 0; g < 4; g++) {
                const uint32_t ad = bufu + (uint32_t)(kro * AROWB + (g * 16 + dco) * 2);
                ldsm4t(vh[g], ad + AVHI);
                ldsm4t(vl[g], ad + AVLO);
            }
            #pragma unroll
            for (int g = 0; g < 4; g++) {
                mma_bf16(oacc[2 * g],     aP[ks], vh[g][0], vh[g][1]);
                mma_bf16(oacc[2 * g + 1], aP[ks], vh[g][2], vh[g][3]);
            }
            #pragma unroll
            for (int g = 0; g < 4; g++) {
                mma_bf16(oacc[2 * g],     aP[ks], vl[g][0], vl[g][1]);
                mma_bf16(oacc[2 * g + 1], aP[ks], vl[g][2], vl[g][3]);
            }
        }
    }

    l0 += __shfl_xor_sync(0xFFFFFFFF, l0, 1);
    l0 += __shfl_xor_sync(0xFFFFFFFF, l0, 2);
    l1 += __shfl_xor_sync(0xFFFFFFFF, l1, 1);
    l1 += __shfl_xor_sync(0xFFFFFFFF, l1, 2);
    const float inv0 = 1.f / l0, inv1 = 1.f / l1;

    const int r1 = qbase + wid * 16 + (lane >> 2);
    const int c0 = (lane & 3) * 2;
    const size_t o1 = (kvrow0 + r1) * 1024 + hcol;
    const size_t o2 = o1 + 8 * 1024;
    #pragma unroll
    for (int j = 0; j < 8; j++) {
        const int cc = j * 8 + c0;
        uint32_t hv, lv;
        split2(oacc[j][0] * inv0, oacc[j][1] * inv0, hv, lv);
        *(uint32_t*)(g_ahi + o1 + cc) = hv;
        *(uint32_t*)(g_alo + o1 + cc) = lv;
        split2(oacc[j][2] * inv1, oacc[j][3] * inv1, hv, lv);
        *(uint32_t*)(g_ahi + o2 + cc) = hv;
        *(uint32_t*)(g_alo + o2 + cc) = lv;
    }
#undef ATTN_ISSUE
}

// =================================================================================
// LayerNorm: out fp32 + optional fp16 hi/lo
// =================================================================================
__global__ void __launch_bounds__(256) layernorm_k(
    const float* __restrict__ in, const float* __restrict__ gamma,
    const float* __restrict__ beta, float* __restrict__ out,
    __half* __restrict__ ohi, __half* __restrict__ olo)
{
    __shared__ float red[256];
    const int row = blockIdx.x;
    const int tid = threadIdx.x;

    const float4 v = ((const float4*)(in + (size_t)row * 1024))[tid];
    float s = v.x + v.y + v.z + v.w;
    red[tid] = s;
    __syncthreads();
    #pragma unroll
    for (int off = 128; off > 0; off >>= 1) {
        if (tid < off) red[tid] += red[tid + off];
        __syncthreads();
    }
    const float mean = red[0] * (1.f / 1024.f);
    __syncthreads();

    const float d0 = v.x - mean, d1 = v.y - mean, d2 = v.z - mean, d3 = v.w - mean;
    s = d0 * d0 + d1 * d1 + d2 * d2 + d3 * d3;
    red[tid] = s;
    __syncthreads();
    #pragma unroll
    for (int off = 128; off > 0; off >>= 1) {
        if (tid < off) red[tid] += red[tid + off];
        __syncthreads();
    }
    const float var = red[0] * (1.f / 1024.f);
    const float inv = 1.f / (sqrtf(var) + LN_EPS);

    const float4 gv = ((const float4*)gamma)[tid];
    const float4 bv = ((const float4*)beta)[tid];
    float4 ov;
    ov.x = gv.x * d0 * inv + bv.x;
    ov.y = gv.y * d1 * inv + bv.y;
    ov.z = gv.z * d2 * inv + bv.z;
    ov.w = gv.w * d3 * inv + bv.w;
    ((float4*)(out + (size_t)row * 1024))[tid] = ov;
    if (ohi) {
        uint32_t h0, l0_, h1, l1_;
        split2h(ov.x, ov.y, h0, l0_);
        split2h(ov.z, ov.w, h1, l1_);
        const size_t o = (size_t)row * 1024 + tid * 4;
        *(uint2*)(ohi + o) = make_uint2(h0, h1);
        *(uint2*)(olo + o) = make_uint2(l0_, l1_);
    }
}

// =================================================================================
// Launch
// =================================================================================
template <typename T>
static T* sym_addr(const void* symbol)
{
    void* p = nullptr;
    cudaGetSymbolAddress(&p, symbol);
    return (T*)p;
}

extern "C" void kernel_launch(void* const* d_in, const int* in_sizes, int n_in,
                              void* d_out, int out_size)
{
    const float* x     = (const float*)d_in[0];
    const float* wq    = (const float*)d_in[1];
    const float* bq    = (const float*)d_in[2];
    const float* wk    = (const float*)d_in[3];
    const float* bk    = (const float*)d_in[4];
    const float* wv    = (const float*)d_in[5];
    const float* bv    = (const float*)d_in[6];
    const float* wo_w  = (const float*)d_in[7];
    const float* wo_b  = (const float*)d_in[8];
    const float* g1    = (const float*)d_in[9];
    const float* b1    = (const float*)d_in[10];
    const float* ff1_w = (const float*)d_in[11];
    const float* ff1_b = (const float*)d_in[12];
    const float* ff2_w = (const float*)d_in[13];
    const float* ff2_b = (const float*)d_in[14];
    const float* g2    = (const float*)d_in[15];
    const float* b2    = (const float*)d_in[16];

    float* q    = sym_addr<float>(g_q);
    float* tmp  = sym_addr<float>(g_tmp);
    float* h    = sym_addr<float>(g_h);
    float* bqkv = sym_addr<float>(g_bqkv);
    __nv_bfloat16* khi = sym_addr<__nv_bfloat16>(g_khi);
    __nv_bfloat16* klo = sym_addr<__nv_bfloat16>(g_klo);
    __nv_bfloat16* vhi = sym_addr<__nv_bfloat16>(g_vhi);
    __nv_bfloat16* vlo = sym_addr<__nv_bfloat16>(g_vlo);
    __nv_bfloat16* xhi = sym_addr<__nv_bfloat16>(g_xhi);
    __nv_bfloat16* xlo = sym_addr<__nv_bfloat16>(g_xlo);
    __nv_bfloat16* ahi = sym_addr<__nv_bfloat16>(g_ahi);
    __nv_bfloat16* alo = sym_addr<__nv_bfloat16>(g_alo);
    __half* hhi = sym_addr<__half>(g_hhi);
    __half* hlo = sym_addr<__half>(g_hlo);
    __half* fhi = sym_addr<__half>(g_fhi);
    __half* flo = sym_addr<__half>(g_flo);
    __nv_bfloat16* wqkvhi = sym_addr<__nv_bfloat16>(g_wqkvhi);
    __nv_bfloat16* wqkvlo = sym_addr<__nv_bfloat16>(g_wqkvlo);
    __nv_bfloat16* wohi = sym_addr<__nv_bfloat16>(g_wohi);
    __nv_bfloat16* wolo = sym_addr<__nv_bfloat16>(g_wolo);
    __half* w1h = sym_addr<__half>(g_w1h);
    __half* w2h = sym_addr<__half>(g_w2h);

    cudaFuncSetAttribute(gemm_cp<0>, cudaFuncAttributeMaxDynamicSharedMemorySize, GSMEM);
    cudaFuncSetAttribute(gemm_cp<1>, cudaFuncAttributeMaxDynamicSharedMemorySize, GSMEM);
    cudaFuncSetAttribute(attn_mma_k, cudaFuncAttributeMaxDynamicSharedMemorySize, ASMEM);

    dim3 tb(32, 8);
    // launches 1-3, then QKV GEMM at slot #4 (ncu capture)
    qkv_tsplit_k<<<dim3(2, 32, 48), tb>>>(wq, wk, wv);
    bias_pack_k<<<12, 256>>>(bq, bk, bv);
    split_k<<<(ROWS * DM) / 256, 256>>>(x, xhi, xlo);

    // 1) fused QKV projection -> Q fp32, K/V bf16 hi/lo          [launch #4]
    gemm_cp<0><<<dim3(24, 16), 512, GSMEM>>>(xhi, xlo, wqkvhi, wqkvlo, bqkv, nullptr,
                                             q, nullptr, nullptr, khi, klo, vhi, vlo,
                                             ROWS, 3 * DM, DM, 0, 2);
    // 2) attention -> ahi/alo (bf16)
    attn_mma_k<<<dim3(SEQ / 128, B_SZ * NH), 256, ASMEM>>>();

    // weight packs
    tsplit_k<<<dim3(32, 32), tb>>>(wo_w, wohi, wolo, DM, DM);
    tsplit_f16_k<<<dim3(64, 32), tb>>>(ff1_w, w1h, DM, DFF);
    tsplit_f16_k<<<dim3(32, 64), tb>>>(ff2_w, w2h, DFF, DM);

    // 3) O-proj + residual(x) -> tmp fp32 (bf16 3-pass)
    gemm_cp<0><<<dim3(8, 16), 512, GSMEM>>>(ahi, alo, wohi, wolo, wo_b, x,
                                            tmp, nullptr, nullptr, nullptr, nullptr, nullptr, nullptr,
                                            ROWS, DM, DM, 0, 0);
    // 4) LN1 -> h fp32 + fp16 hi/lo
    layernorm_k<<<ROWS, 256>>>(tmp, g1, b1, h, hhi, hlo);
    // 5) FF1 + ReLU -> fhi/flo (fp16 2-pass)
    gemm_cp<1><<<dim3(16, 16), 512, GSMEM>>>((const __nv_bfloat16*)hhi, (const __nv_bfloat16*)hlo,
                                             (const __nv_bfloat16*)w1h, nullptr, ff1_b, nullptr,
                                             nullptr, (__nv_bfloat16*)fhi, (__nv_bfloat16*)flo,
                                             nullptr, nullptr, nullptr, nullptr,
                                             ROWS, DFF, DM, 1, 1);
    // 6) FF2 + residual(h) -> tmp fp32 (fp16 2-pass)
    gemm_cp<1><<<dim3(8, 16), 512, GSMEM>>>((const __nv_bfloat16*)fhi, (const __nv_bfloat16*)flo,
                                            (const __nv_bfloat16*)w2h, nullptr, ff2_b, h,
                                            tmp, nullptr, nullptr, nullptr, nullptr, nullptr, nullptr,
                                            ROWS, DM, DFF, 0, 0);
    // 7) LN2 -> output
    layernorm_k<<<ROWS, 256>>>(tmp, g2, b2, (float*)d_out, nullptr, nullptr);
}

// round 12
// speedup vs baseline: 1.2569x; 1.1160x over previous
#include <cuda_runtime.h>
#include <cuda_bf16.h>
#include <cuda_fp16.h>
#include <math.h>
#include <cstdint>

#define B_SZ   4
#define SEQ    1024
#define DM     1024
#define NH     16
#define DFF    2048
#define ROWS   (B_SZ*SEQ)        // 4096
#define LN_EPS 1e-5f

// GEMM smem: CTA tile 256x128, chunk k64, fp16 2-pass. Row stride 144B.
// Per buffer: Ahi/Alo 256x144, Bhi 128x144.
#define ROWB      144
#define OFF_AHI   0
#define OFF_ALO   36864
#define OFF_BHI   73728
#define BUF_B     92160
#define GSMEM     (2*BUF_B)      // 184320

// Attention smem (bf16, unchanged)
#define AROWB     144
#define ATILE     (64*AROWB)
#define AKHI      0
#define AKLO      (ATILE)
#define AVHI      (2*ATILE)
#define AVLO      (3*ATILE)
#define ABUF      (4*ATILE)
#define ASMEM     (2*ABUF)

// ---------------- scratch (device globals) ----------------
__device__ float g_q[ROWS*DM];
__device__ float g_tmp[ROWS*DM];
__device__ float g_h[ROWS*DM];
__device__ float g_bqkv[3*DM];
__device__ __nv_bfloat16 g_khi[ROWS*DM],   g_klo[ROWS*DM];
__device__ __nv_bfloat16 g_vhi[ROWS*DM],   g_vlo[ROWS*DM];
__device__ __half        g_xhi[ROWS*DM],   g_xlo[ROWS*DM];        // x fp16 hi/lo
__device__ __half        g_ahi[ROWS*DM],   g_alo[ROWS*DM];        // attention out fp16
__device__ __half        g_hhi[ROWS*DM],   g_hlo[ROWS*DM];        // LN1 out fp16
__device__ __half        g_fhi[ROWS*DFF],  g_flo[ROWS*DFF];       // FF1 out fp16
__device__ __half        g_wqkvh[3*DM*DM];                        // [3072 N][1024 K] fp16 hi
__device__ __half        g_woh[DM*DM];
__device__ __half        g_w1h[DFF*DM];
__device__ __half        g_w2h[DM*DFF];

// =================================================================================
// helpers
// =================================================================================
__device__ __forceinline__ uint32_t smem_u32(const void* p) {
    uint32_t a;
    asm("{ .reg .u64 t; cvta.to.shared.u64 t, %1; cvt.u32.u64 %0, t; }" : "=r"(a) : "l"(p));
    return a;
}
__device__ __forceinline__ void ldsm4(uint32_t* r, uint32_t addr) {
    asm volatile("ldmatrix.sync.aligned.m8n8.x4.shared.b16 {%0,%1,%2,%3}, [%4];"
                 : "=r"(r[0]), "=r"(r[1]), "=r"(r[2]), "=r"(r[3]) : "r"(addr));
}
__device__ __forceinline__ void ldsm4t(uint32_t* r, uint32_t addr) {
    asm volatile("ldmatrix.sync.aligned.m8n8.x4.trans.shared.b16 {%0,%1,%2,%3}, [%4];"
                 : "=r"(r[0]), "=r"(r[1]), "=r"(r[2]), "=r"(r[3]) : "r"(addr));
}
__device__ __forceinline__ void mma_bf16(float* d, const uint32_t* a, uint32_t b0, uint32_t b1) {
    asm volatile("mma.sync.aligned.m16n8k16.row.col.f32.bf16.bf16.f32 "
                 "{%0,%1,%2,%3}, {%4,%5,%6,%7}, {%8,%9}, {%0,%1,%2,%3};"
                 : "+f"(d[0]), "+f"(d[1]), "+f"(d[2]), "+f"(d[3])
                 : "r"(a[0]), "r"(a[1]), "r"(a[2]), "r"(a[3]), "r"(b0), "r"(b1));
}
__device__ __forceinline__ void mma_f16(float* d, const uint32_t* a, uint32_t b0, uint32_t b1) {
    asm volatile("mma.sync.aligned.m16n8k16.row.col.f32.f16.f16.f32 "
                 "{%0,%1,%2,%3}, {%4,%5,%6,%7}, {%8,%9}, {%0,%1,%2,%3};"
                 : "+f"(d[0]), "+f"(d[1]), "+f"(d[2]), "+f"(d[3])
                 : "r"(a[0]), "r"(a[1]), "r"(a[2]), "r"(a[3]), "r"(b0), "r"(b1));
}
#define CP16(dst, src) asm volatile("cp.async.cg.shared.global [%0], [%1], 16;" :: "r"(dst), "l"(src))
#define CP_COMMIT()    asm volatile("cp.async.commit_group;" ::: "memory")
#define CP_WAIT(n)     asm volatile("cp.async.wait_group %0;" :: "n"(n) : "memory")

__device__ __forceinline__ void split2(float a, float b, uint32_t& hi, uint32_t& lo) {
    __nv_bfloat16 ah = __float2bfloat16(a);
    __nv_bfloat16 bh = __float2bfloat16(b);
    __nv_bfloat16 al = __float2bfloat16(a - __bfloat162float(ah));
    __nv_bfloat16 bl = __float2bfloat16(b - __bfloat162float(bh));
    __nv_bfloat162 h2; h2.x = ah; h2.y = bh;
    __nv_bfloat162 l2; l2.x = al; l2.y = bl;
    hi = *reinterpret_cast<uint32_t*>(&h2);
    lo = *reinterpret_cast<uint32_t*>(&l2);
}
__device__ __forceinline__ void split2h(float a, float b, uint32_t& hi, uint32_t& lo) {
    __half ah = __float2half_rn(a);
    __half bh = __float2half_rn(b);
    __half al = __float2half_rn(a - __half2float(ah));
    __half bl = __float2half_rn(b - __half2float(bh));
    __half2 h2; h2.x = ah; h2.y = bh;
    __half2 l2; l2.x = al; l2.y = bl;
    hi = *reinterpret_cast<uint32_t*>(&h2);
    lo = *reinterpret_cast<uint32_t*>(&l2);
}
__device__ __forceinline__ uint32_t packbf(float a, float b) {
    __nv_bfloat162 t; t.x = __float2bfloat16(a); t.y = __float2bfloat16(b);
    return *reinterpret_cast<uint32_t*>(&t);
}

// =================================================================================
// weight packing
// =================================================================================
// transpose + fp16 (hi only): src [R][C] fp32 -> dst [C][R] fp16
__global__ void tsplit_f16_k(const float* __restrict__ src,
                             __half* __restrict__ dhi, int R, int C)
{
    __shared__ float t[32][33];
    const int c0 = blockIdx.x * 32, r0 = blockIdx.y * 32;
    const int tx = threadIdx.x, ty = threadIdx.y;
    #pragma unroll
    for (int i = ty; i < 32; i += 8)
        t[i][tx] = src[(size_t)(r0 + i) * C + c0 + tx];
    __syncthreads();
    #pragma unroll
    for (int i = ty; i < 32; i += 8)
        dhi[(size_t)(c0 + i) * R + r0 + tx] = __float2half_rn(t[tx][i]);
}

// QKV weights -> fp16 hi at [n=t*1024+h*64+d][k]
__global__ void qkv_tsplit_k(const float* __restrict__ wq, const float* __restrict__ wk,
                             const float* __restrict__ wv)
{
    __shared__ float t[32][33];
    const int z = blockIdx.z;
    const int ts = z >> 4, h = z & 15;
    const float* w = ((ts == 0) ? wq : (ts == 1) ? wk : wv) + (size_t)h * 1024 * 64;
    const int d0 = blockIdx.x * 32, k0 = blockIdx.y * 32;
    const int tx = threadIdx.x, ty = threadIdx.y;
    #pragma unroll
    for (int i = ty; i < 32; i += 8)
        t[i][tx] = w[(size_t)(k0 + i) * 64 + d0 + tx];
    __syncthreads();
    #pragma unroll
    for (int i = ty; i < 32; i += 8)
        g_wqkvh[(size_t)(ts * 1024 + h * 64 + d0 + i) * 1024 + k0 + tx] = __float2half_rn(t[tx][i]);
}

__global__ void bias_pack_k(const float* __restrict__ bq, const float* __restrict__ bk,
                            const float* __restrict__ bv)
{
    const int n = blockIdx.x * 256 + threadIdx.x;
    if (n < 3072) {
        const int t = n >> 10, rem = n & 1023;
        g_bqkv[n] = ((t == 0) ? bq : (t == 1) ? bk : bv)[rem];
    }
}

// elementwise fp32 -> fp16 hi/lo
__global__ void split_f16_k(const float* __restrict__ src,
                            __half* __restrict__ dhi, __half* __restrict__ dlo)
{
    const int i = blockIdx.x * 256 + threadIdx.x;
    const float v = src[i];
    const __half h = __float2half_rn(v);
    dhi[i] = h;
    dlo[i] = __float2half_rn(v - __half2float(h));
}

// =================================================================================
// cp.async fp16 2-pass GEMM: D = (Ahi + Alo) x Bhi. CTA 256x128, 512 threads,
// 16 warps of 64x32, k64 chunks, 2-stage pipeline.
// mode 0: Cf = acc + bias (+res).  mode 1: Chi/Clo fp16 = acc + bias (relu opt).
// mode 2 (QKV): col<1024 -> Cf (fp32 Q); 1024..2047 -> K bf16 hi/lo; 2048.. -> V bf16 hi/lo.
// =================================================================================
__global__ void __launch_bounds__(512) gemm_cp(
    const __half* __restrict__ Ahi, const __half* __restrict__ Alo,
    const __half* __restrict__ Bhi,
    const float* __restrict__ bias, const float* __restrict__ res,
    float* __restrict__ Cf,
    __half* __restrict__ Chi, __half* __restrict__ Clo,
    __nv_bfloat16* __restrict__ Khi, __nv_bfloat16* __restrict__ Klo,
    __nv_bfloat16* __restrict__ Vhi, __nv_bfloat16* __restrict__ Vlo,
    int M, int N, int K, int relu, int mode)
{
    extern __shared__ __align__(128) char sm[];
    const uint32_t sbase = smem_u32(sm);

    const int tid  = threadIdx.x;
    const int wid  = tid >> 5;
    const int lane = tid & 31;
    const int bm = blockIdx.y * 256;
    const int bn = blockIdx.x * 128;
    const int warp_m = wid & 3;
    const int warp_n = wid >> 2;

    const int r0 = tid >> 2;
    const int ch = tid & 3;
    const __half* pAh = Ahi + (size_t)(bm + r0) * K + ch * 8;
    const __half* pAl = Alo + (size_t)(bm + r0) * K + ch * 8;
    const __half* pBh = Bhi + (size_t)(bn + r0) * K + ch * 8;
    const size_t arow2 = (size_t)128 * K;
    const uint32_t sA0 = (uint32_t)(r0 * ROWB + ch * 16);
    const uint32_t sA1 = sA0 + 128 * ROWB;

    auto issue = [&](uint32_t dbuf, int k0) {
        CP16(dbuf + OFF_AHI + sA0,      pAh + k0);
        CP16(dbuf + OFF_AHI + sA0 + 64, pAh + k0 + 32);
        CP16(dbuf + OFF_AHI + sA1,      pAh + k0 + arow2);
        CP16(dbuf + OFF_AHI + sA1 + 64, pAh + k0 + arow2 + 32);
        CP16(dbuf + OFF_ALO + sA0,      pAl + k0);
        CP16(dbuf + OFF_ALO + sA0 + 64, pAl + k0 + 32);
        CP16(dbuf + OFF_ALO + sA1,      pAl + k0 + arow2);
        CP16(dbuf + OFF_ALO + sA1 + 64, pAl + k0 + arow2 + 32);
        CP16(dbuf + OFF_BHI + sA0,      pBh + k0);
        CP16(dbuf + OFF_BHI + sA0 + 64, pBh + k0 + 32);
    };

    float acc[4][4][4];
    #pragma unroll
    for (int i = 0; i < 4; i++)
        #pragma unroll
        for (int j = 0; j < 4; j++)
            #pragma unroll
            for (int q = 0; q < 4; q++) acc[i][j][q] = 0.f;

    const int NCH = K >> 6;

    issue(sbase, 0); CP_COMMIT();

    for (int c = 0; c < NCH; c++) {
        CP_WAIT(0);
        __syncthreads();
        if (c + 1 < NCH) {
            issue(sbase + (uint32_t)((c + 1) & 1) * BUF_B, (c + 1) * 64);
            CP_COMMIT();
        }
        const uint32_t buf = sbase + (uint32_t)(c & 1) * BUF_B;

        #pragma unroll
        for (int ks = 0; ks < 4; ks++) {
            const int arow = warp_m * 64 + (lane & 15);
            const int acol = ks * 16 + (lane >> 4) * 8;
            const int nrow = warp_n * 32 + ((lane >> 4) << 3) + (lane & 7);
            const int bcol = ks * 16 + ((lane >> 3) & 1) * 8;

            // pass 1: hi x hi
            uint32_t a_hi[4][4], b_hi[2][4];
            #pragma unroll
            for (int im = 0; im < 4; im++)
                ldsm4(a_hi[im], buf + OFF_AHI + (uint32_t)((arow + im * 16) * ROWB + acol * 2));
            #pragma unroll
            for (int jb = 0; jb < 2; jb++)
                ldsm4(b_hi[jb], buf + OFF_BHI + (uint32_t)((nrow + jb * 16) * ROWB + bcol * 2));
            #pragma unroll
            for (int im = 0; im < 4; im++)
                #pragma unroll
                for (int jn = 0; jn < 4; jn++) {
                    const int jb = jn >> 1, sl = (jn & 1) * 2;
                    mma_f16(acc[im][jn], a_hi[im], b_hi[jb][sl], b_hi[jb][sl + 1]);
                }
            // pass 2: lo x hi
            {
                uint32_t a_lo[4][4];
                #pragma unroll
                for (int im = 0; im < 4; im++)
                    ldsm4(a_lo[im], buf + OFF_ALO + (uint32_t)((arow + im * 16) * ROWB + acol * 2));
                #pragma unroll
                for (int im = 0; im < 4; im++)
                    #pragma unroll
                    for (int jn = 0; jn < 4; jn++) {
                        const int jb = jn >> 1, sl = (jn & 1) * 2;
                        mma_f16(acc[im][jn], a_lo[im], b_hi[jb][sl], b_hi[jb][sl + 1]);
                    }
            }
        }
    }

    // ---- epilogue ----
    const int row0 = bm + warp_m * 64 + (lane >> 2);
    const int col0 = bn + warp_n * 32 + (lane & 3) * 2;
    const int sel = bn >> 10;
    #pragma unroll
    for (int im = 0; im < 4; im++) {
        #pragma unroll
        for (int half = 0; half < 2; half++) {
            const int r = row0 + im * 16 + half * 8;
            #pragma unroll
            for (int jn = 0; jn < 4; jn++) {
                const int cc = col0 + jn * 8;
                float2 o;
                o.x = acc[im][jn][2 * half]     + bias[cc];
                o.y = acc[im][jn][2 * half + 1] + bias[cc + 1];
                if (mode == 0) {
                    if (res) {
                        const float2 rv = *(const float2*)(res + (size_t)r * N + cc);
                        o.x += rv.x; o.y += rv.y;
                    }
                    *(float2*)(Cf + (size_t)r * N + cc) = o;
                } else if (mode == 1) {
                    if (relu) { o.x = fmaxf(o.x, 0.f); o.y = fmaxf(o.y, 0.f); }
                    uint32_t hv, lv;
                    split2h(o.x, o.y, hv, lv);
                    *(uint32_t*)(Chi + (size_t)r * N + cc) = hv;
                    *(uint32_t*)(Clo + (size_t)r * N + cc) = lv;
                } else {
                    const int lc = cc - (sel << 10);
                    if (sel == 0) {
                        *(float2*)(Cf + (size_t)r * 1024 + lc) = o;
                    } else {
                        uint32_t hv, lv;
                        split2(o.x, o.y, hv, lv);
                        __nv_bfloat16* dh = (sel == 1) ? Khi : Vhi;
                        __nv_bfloat16* dl = (sel == 1) ? Klo : Vlo;
                        *(uint32_t*)(dh + (size_t)r * 1024 + lc) = hv;
                        *(uint32_t*)(dl + (size_t)r * 1024 + lc) = lv;
                    }
                }
            }
        }
    }
}

// =================================================================================
// Tensor-core flash attention (bf16 internals); epilogue writes fp16 hi/lo.
// =================================================================================
__global__ void __launch_bounds__(256) attn_mma_k()
{
    extern __shared__ __align__(128) char asmem[];
    const uint32_t sbase = smem_u32(asmem);
    const int tid  = threadIdx.x;
    const int wid  = tid >> 5;
    const int lane = tid & 31;
    const int bhid = blockIdx.y;
    const int bb = bhid >> 4, hh = bhid & 15;
    const int qbase = blockIdx.x * 128;
    const size_t kvrow0 = (size_t)bb * 1024;
    const int hcol = hh * 64;

    float* Qf = (float*)asmem;
    for (int i = tid; i < 128 * 64; i += 256) {
        const int r = i >> 6, c = i & 63;
        Qf[r * 68 + c] = g_q[(kvrow0 + qbase + r) * 1024 + hcol + c] * 0.125f;
    }
    __syncthreads();

    uint32_t qhi[4][4], qlo[4][4];
    {
        const int r1 = wid * 16 + (lane >> 2);
        const int c0 = (lane & 3) * 2;
        #pragma unroll
        for (int t = 0; t < 4; t++)
            #pragma unroll
            for (int q = 0; q < 4; q++) {
                const int rr = r1 + (q & 1) * 8;
                const int cc = t * 16 + c0 + (q >> 1) * 8;
                split2(Qf[rr * 68 + cc], Qf[rr * 68 + cc + 1], qhi[t][q], qlo[t][q]);
            }
    }
    __syncthreads();

#define ATTN_ISSUE(dbuf, t) do { \
    _Pragma("unroll") \
    for (int u = 0; u < 2; u++) { \
        const int id = tid + u * 256; \
        const int row = id >> 3, c8 = id & 7; \
        const uint32_t off = (uint32_t)(row * AROWB + c8 * 16); \
        const size_t gl = (kvrow0 + (t) * 64 + row) * 1024 + hcol + c8 * 8; \
        CP16((dbuf) + AKHI + off, g_khi + gl); \
        CP16((dbuf) + AKLO + off, g_klo + gl); \
        CP16((dbuf) + AVHI + off, g_vhi + gl); \
        CP16((dbuf) + AVLO + off, g_vlo + gl); \
    } \
} while (0)

    float oacc[8][4];
    #pragma unroll
    for (int j = 0; j < 8; j++)
        #pragma unroll
        for (int q = 0; q < 4; q++) oacc[j][q] = 0.f;
    float m0 = -1e30f, m1 = -1e30f, l0 = 0.f, l1 = 0.f;

    ATTN_ISSUE(sbase, 0); CP_COMMIT();

    for (int t = 0; t < 16; t++) {
        CP_WAIT(0);
        __syncthreads();
        if (t + 1 < 16) {
            ATTN_ISSUE(sbase + (uint32_t)((t + 1) & 1) * ABUF, t + 1);
            CP_COMMIT();
        }
        const uint32_t bufu = sbase + (uint32_t)(t & 1) * ABUF;

        float s[8][4];
        #pragma unroll
        for (int j = 0; j < 8; j++)
            #pragma unroll
            for (int q = 0; q < 4; q++) s[j][q] = 0.f;

        #pragma unroll
        for (int ks = 0; ks < 4; ks++) {
            uint32_t kh[4][4], kl[4][4];
            const int nro = ((lane >> 4) << 3) + (lane & 7);
            const int kco = ks * 16 + ((lane >> 3) & 1) * 8;
            #pragma unroll
            for (int g = 0; g < 4; g++) {
                const uint32_t ad = bufu + (uint32_t)((g * 16 + nro) * AROWB + kco * 2);
                ldsm4(kh[g], ad + AKHI);
                ldsm4(kl[g], ad + AKLO);
            }
            #pragma unroll
            for (int g = 0; g < 4; g++) {
                mma_bf16(s[2 * g],     qhi[ks], kh[g][0], kh[g][1]);
                mma_bf16(s[2 * g + 1], qhi[ks], kh[g][2], kh[g][3]);
            }
            #pragma unroll
            for (int g = 0; g < 4; g++) {
                mma_bf16(s[2 * g],     qhi[ks], kl[g][0], kl[g][1]);
                mma_bf16(s[2 * g + 1], qhi[ks], kl[g][2], kl[g][3]);
            }
            #pragma unroll
            for (int g = 0; g < 4; g++) {
                mma_bf16(s[2 * g],     qlo[ks], kh[g][0], kh[g][1]);
                mma_bf16(s[2 * g + 1], qlo[ks], kh[g][2], kh[g][3]);
            }
        }

        float mx0 = s[0][0], mx1 = s[0][2];
        #pragma unroll
        for (int j = 0; j < 8; j++) {
            mx0 = fmaxf(mx0, fmaxf(s[j][0], s[j][1]));
            mx1 = fmaxf(mx1, fmaxf(s[j][2], s[j][3]));
        }
        mx0 = fmaxf(mx0, __shfl_xor_sync(0xFFFFFFFF, mx0, 1));
        mx0 = fmaxf(mx0, __shfl_xor_sync(0xFFFFFFFF, mx0, 2));
        mx1 = fmaxf(mx1, __shfl_xor_sync(0xFFFFFFFF, mx1, 1));
        mx1 = fmaxf(mx1, __shfl_xor_sync(0xFFFFFFFF, mx1, 2));
        const float nm0 = fmaxf(m0, mx0), nm1 = fmaxf(m1, mx1);
        const float sc0 = __expf(m0 - nm0), sc1 = __expf(m1 - nm1);
        m0 = nm0; m1 = nm1;
        l0 *= sc0; l1 *= sc1;
        #pragma unroll
        for (int j = 0; j < 8; j++) {
            oacc[j][0] *= sc0; oacc[j][1] *= sc0;
            oacc[j][2] *= sc1; oacc[j][3] *= sc1;
        }

        uint32_t aP[4][4];
        #pragma unroll
        for (int j = 0; j < 8; j++) {
            const float p0 = __expf(s[j][0] - m0);
            const float p1 = __expf(s[j][1] - m0);
            const float p2 = __expf(s[j][2] - m1);
            const float p3 = __expf(s[j][3] - m1);
            l0 += p0 + p1;
            l1 += p2 + p3;
            const int kt = j >> 1;
            if ((j & 1) == 0) { aP[kt][0] = packbf(p0, p1); aP[kt][1] = packbf(p2, p3); }
            else              { aP[kt][2] = packbf(p0, p1); aP[kt][3] = packbf(p2, p3); }
        }

        #pragma unroll
        for (int ks = 0; ks < 4; ks++) {
            uint32_t vh[4][4], vl[4][4];
            const int kro = ks * 16 + ((lane >> 3) & 1) * 8 + (lane & 7);
            const int dco = ((lane >> 4) & 1) * 8;
            #pragma unroll
            for (int g = 0; g < 4; g++) {
                const uint32_t ad = bufu + (uint32_t)(kro * AROWB + (g * 16 + dco) * 2);
                ldsm4t(vh[g], ad + AVHI);
                ldsm4t(vl[g], ad + AVLO);
            }
            #pragma unroll
            for (int g = 0; g < 4; g++) {
                mma_bf16(oacc[2 * g],     aP[ks], vh[g][0], vh[g][1]);
                mma_bf16(oacc[2 * g + 1], aP[ks], vh[g][2], vh[g][3]);
            }
            #pragma unroll
            for (int g = 0; g < 4; g++) {
                mma_bf16(oacc[2 * g],     aP[ks], vl[g][0], vl[g][1]);
                mma_bf16(oacc[2 * g + 1], aP[ks], vl[g][2], vl[g][3]);
            }
        }
    }

    l0 += __shfl_xor_sync(0xFFFFFFFF, l0, 1);
    l0 += __shfl_xor_sync(0xFFFFFFFF, l0, 2);
    l1 += __shfl_xor_sync(0xFFFFFFFF, l1, 1);
    l1 += __shfl_xor_sync(0xFFFFFFFF, l1, 2);
    const float inv0 = 1.f / l0, inv1 = 1.f / l1;

    const int r1 = qbase + wid * 16 + (lane >> 2);
    const int c0 = (lane & 3) * 2;
    const size_t o1 = (kvrow0 + r1) * 1024 + hcol;
    const size_t o2 = o1 + 8 * 1024;
    #pragma unroll
    for (int j = 0; j < 8; j++) {
        const int cc = j * 8 + c0;
        uint32_t hv, lv;
        split2h(oacc[j][0] * inv0, oacc[j][1] * inv0, hv, lv);
        *(uint32_t*)(g_ahi + o1 + cc) = hv;
        *(uint32_t*)(g_alo + o1 + cc) = lv;
        split2h(oacc[j][2] * inv1, oacc[j][3] * inv1, hv, lv);
        *(uint32_t*)(g_ahi + o2 + cc) = hv;
        *(uint32_t*)(g_alo + o2 + cc) = lv;
    }
#undef ATTN_ISSUE
}

// =================================================================================
// LayerNorm: out fp32 + optional fp16 hi/lo
// =================================================================================
__global__ void __launch_bounds__(256) layernorm_k(
    const float* __restrict__ in, const float* __restrict__ gamma,
    const float* __restrict__ beta, float* __restrict__ out,
    __half* __restrict__ ohi, __half* __restrict__ olo)
{
    __shared__ float red[256];
    const int row = blockIdx.x;
    const int tid = threadIdx.x;

    const float4 v = ((const float4*)(in + (size_t)row * 1024))[tid];
    float s = v.x + v.y + v.z + v.w;
    red[tid] = s;
    __syncthreads();
    #pragma unroll
    for (int off = 128; off > 0; off >>= 1) {
        if (tid < off) red[tid] += red[tid + off];
        __syncthreads();
    }
    const float mean = red[0] * (1.f / 1024.f);
    __syncthreads();

    const float d0 = v.x - mean, d1 = v.y - mean, d2 = v.z - mean, d3 = v.w - mean;
    s = d0 * d0 + d1 * d1 + d2 * d2 + d3 * d3;
    red[tid] = s;
    __syncthreads();
    #pragma unroll
    for (int off = 128; off > 0; off >>= 1) {
        if (tid < off) red[tid] += red[tid + off];
        __syncthreads();
    }
    const float var = red[0] * (1.f / 1024.f);
    const float inv = 1.f / (sqrtf(var) + LN_EPS);

    const float4 gv = ((const float4*)gamma)[tid];
    const float4 bv = ((const float4*)beta)[tid];
    float4 ov;
    ov.x = gv.x * d0 * inv + bv.x;
    ov.y = gv.y * d1 * inv + bv.y;
    ov.z = gv.z * d2 * inv + bv.z;
    ov.w = gv.w * d3 * inv + bv.w;
    ((float4*)(out + (size_t)row * 1024))[tid] = ov;
    if (ohi) {
        uint32_t h0, l0_, h1, l1_;
        split2h(ov.x, ov.y, h0, l0_);
        split2h(ov.z, ov.w, h1, l1_);
        const size_t o = (size_t)row * 1024 + tid * 4;
        *(uint2*)(ohi + o) = make_uint2(h0, h1);
        *(uint2*)(olo + o) = make_uint2(l0_, l1_);
    }
}

// =================================================================================
// Launch
// =================================================================================
template <typename T>
static T* sym_addr(const void* symbol)
{
    void* p = nullptr;
    cudaGetSymbolAddress(&p, symbol);
    return (T*)p;
}

extern "C" void kernel_launch(void* const* d_in, const int* in_sizes, int n_in,
                              void* d_out, int out_size)
{
    const float* x     = (const float*)d_in[0];
    const float* wq    = (const float*)d_in[1];
    const float* bq    = (const float*)d_in[2];
    const float* wk    = (const float*)d_in[3];
    const float* bk    = (const float*)d_in[4];
    const float* wv    = (const float*)d_in[5];
    const float* bv    = (const float*)d_in[6];
    const float* wo_w  = (const float*)d_in[7];
    const float* wo_b  = (const float*)d_in[8];
    const float* g1    = (const float*)d_in[9];
    const float* b1    = (const float*)d_in[10];
    const float* ff1_w = (const float*)d_in[11];
    const float* ff1_b = (const float*)d_in[12];
    const float* ff2_w = (const float*)d_in[13];
    const float* ff2_b = (const float*)d_in[14];
    const float* g2    = (const float*)d_in[15];
    const float* b2    = (const float*)d_in[16];

    float* q    = sym_addr<float>(g_q);
    float* tmp  = sym_addr<float>(g_tmp);
    float* h    = sym_addr<float>(g_h);
    float* bqkv = sym_addr<float>(g_bqkv);
    __nv_bfloat16* khi = sym_addr<__nv_bfloat16>(g_khi);
    __nv_bfloat16* klo = sym_addr<__nv_bfloat16>(g_klo);
    __nv_bfloat16* vhi = sym_addr<__nv_bfloat16>(g_vhi);
    __nv_bfloat16* vlo = sym_addr<__nv_bfloat16>(g_vlo);
    __half* xhi = sym_addr<__half>(g_xhi);
    __half* xlo = sym_addr<__half>(g_xlo);
    __half* ahi = sym_addr<__half>(g_ahi);
    __half* alo = sym_addr<__half>(g_alo);
    __half* hhi = sym_addr<__half>(g_hhi);
    __half* hlo = sym_addr<__half>(g_hlo);
    __half* fhi = sym_addr<__half>(g_fhi);
    __half* flo = sym_addr<__half>(g_flo);
    __half* wqkvh = sym_addr<__half>(g_wqkvh);
    __half* woh = sym_addr<__half>(g_woh);
    __half* w1h = sym_addr<__half>(g_w1h);
    __half* w2h = sym_addr<__half>(g_w2h);

    cudaFuncSetAttribute(gemm_cp, cudaFuncAttributeMaxDynamicSharedMemorySize, GSMEM);
    cudaFuncSetAttribute(attn_mma_k, cudaFuncAttributeMaxDynamicSharedMemorySize, ASMEM);

    dim3 tb(32, 8);
    // launches 1-3, QKV GEMM at slot #4 (ncu capture)
    qkv_tsplit_k<<<dim3(2, 32, 48), tb>>>(wq, wk, wv);
    bias_pack_k<<<12, 256>>>(bq, bk, bv);
    split_f16_k<<<(ROWS * DM) / 256, 256>>>(x, xhi, xlo);

    // 1) fused QKV projection (fp16 2-pass) -> Q fp32, K/V bf16 hi/lo   [launch #4]
    gemm_cp<<<dim3(24, 16), 512, GSMEM>>>(xhi, xlo, wqkvh, bqkv, nullptr,
                                          q, nullptr, nullptr, khi, klo, vhi, vlo,
                                          ROWS, 3 * DM, DM, 0, 2);
    // 2) attention -> ahi/alo (fp16)
    attn_mma_k<<<dim3(SEQ / 128, B_SZ * NH), 256, ASMEM>>>();

    // weight packs
    tsplit_f16_k<<<dim3(32, 32), tb>>>(wo_w, woh, DM, DM);
    tsplit_f16_k<<<dim3(64, 32), tb>>>(ff1_w, w1h, DM, DFF);
    tsplit_f16_k<<<dim3(32, 64), tb>>>(ff2_w, w2h, DFF, DM);

    // 3) O-proj + residual(x) -> tmp fp32 (fp16 2-pass)
    gemm_cp<<<dim3(8, 16), 512, GSMEM>>>(ahi, alo, woh, wo_b, x,
                                         tmp, nullptr, nullptr, nullptr, nullptr, nullptr, nullptr,
                                         ROWS, DM, DM, 0, 0);
    // 4) LN1 -> h fp32 + fp16 hi/lo
    layernorm_k<<<ROWS, 256>>>(tmp, g1, b1, h, hhi, hlo);
    // 5) FF1 + ReLU -> fhi/flo (fp16 2-pass)
    gemm_cp<<<dim3(16, 16), 512, GSMEM>>>(hhi, hlo, w1h, ff1_b, nullptr,
                                          nullptr, fhi, flo, nullptr, nullptr, nullptr, nullptr,
                                          ROWS, DFF, DM, 1, 1);
    // 6) FF2 + residual(h) -> tmp fp32 (fp16 2-pass)
    gemm_cp<<<dim3(8, 16), 512, GSMEM>>>(fhi, flo, w2h, ff2_b, h,
                                         tmp, nullptr, nullptr, nullptr, nullptr, nullptr, nullptr,
                                         ROWS, DM, DFF, 0, 0);
    // 7) LN2 -> output
    layernorm_k<<<ROWS, 256>>>(tmp, g2, b2, (float*)d_out, nullptr, nullptr);
}